// round 4
// baseline (speedup 1.0000x reference)
#include <cuda_runtime.h>
#include <cuda_bf16.h>
#include <math.h>
#include <stdint.h>

// ---------------- problem constants ----------------
#define BB   4
#define SS   1024
#define DD   1024
#define HH   16
#define HDIM 64
#define LL   2
#define DFF  4096
#define MM   (BB*SS)

// ---------------- static device scratch ----------------
__device__ __align__(256) float g_scores[(size_t)BB*HH*SS*SS];    // 268MB
__device__ __align__(256) float g_tmp [(size_t)MM*DD];
__device__ __align__(256) float g_attn[(size_t)MM*DD];
__device__ __align__(256) float g_hs  [(size_t)MM*DD];

__device__ __align__(256) __nv_bfloat16 g_hs_h [(size_t)MM*DD];
__device__ __align__(256) __nv_bfloat16 g_hs_l [(size_t)MM*DD];
__device__ __align__(256) __nv_bfloat16 g_q_h  [(size_t)MM*DD];
__device__ __align__(256) __nv_bfloat16 g_q_l  [(size_t)MM*DD];
__device__ __align__(256) __nv_bfloat16 g_k_h  [(size_t)MM*DD];
__device__ __align__(256) __nv_bfloat16 g_k_l  [(size_t)MM*DD];
__device__ __align__(256) __nv_bfloat16 g_v_h  [(size_t)MM*DD];
__device__ __align__(256) __nv_bfloat16 g_v_l  [(size_t)MM*DD];
__device__ __align__(256) __nv_bfloat16 g_ctx_h[(size_t)MM*DD];
__device__ __align__(256) __nv_bfloat16 g_ctx_l[(size_t)MM*DD];
__device__ __align__(256) __nv_bfloat16 g_attn_h[(size_t)MM*DD];
__device__ __align__(256) __nv_bfloat16 g_attn_l[(size_t)MM*DD];
__device__ __align__(256) __nv_bfloat16 g_ffn1_h[(size_t)MM*DFF];
__device__ __align__(256) __nv_bfloat16 g_ffn1_l[(size_t)MM*DFF];
__device__ __align__(256) __nv_bfloat16 g_p_h  [(size_t)BB*HH*SS*SS];
__device__ __align__(256) __nv_bfloat16 g_p_l  [(size_t)BB*HH*SS*SS];

__device__ __align__(256) __nv_bfloat16 g_wq_h[(size_t)DD*DD];
__device__ __align__(256) __nv_bfloat16 g_wq_l[(size_t)DD*DD];
__device__ __align__(256) __nv_bfloat16 g_wk_h[(size_t)DD*DD];
__device__ __align__(256) __nv_bfloat16 g_wk_l[(size_t)DD*DD];
__device__ __align__(256) __nv_bfloat16 g_wv_h[(size_t)DD*DD];
__device__ __align__(256) __nv_bfloat16 g_wv_l[(size_t)DD*DD];
__device__ __align__(256) __nv_bfloat16 g_wo_h[(size_t)DD*DD];
__device__ __align__(256) __nv_bfloat16 g_wo_l[(size_t)DD*DD];
__device__ __align__(256) __nv_bfloat16 g_w1_h[(size_t)LL*DD*DFF];
__device__ __align__(256) __nv_bfloat16 g_w1_l[(size_t)LL*DD*DFF];
__device__ __align__(256) __nv_bfloat16 g_w2_h[(size_t)LL*DFF*DD];
__device__ __align__(256) __nv_bfloat16 g_w2_l[(size_t)LL*DFF*DD];

// ---------------- asm helpers ----------------
__device__ __forceinline__ uint32_t smem_u32(const void* p) {
    uint32_t a;
    asm("{ .reg .u64 t; cvta.to.shared.u64 t, %1; cvt.u32.u64 %0, t; }"
        : "=r"(a) : "l"(p));
    return a;
}
#define CP16(dst, src) asm volatile("cp.async.cg.shared.global [%0], [%1], 16;" :: "r"(dst), "l"(src) : "memory")
#define CPCOMMIT()     asm volatile("cp.async.commit_group;" ::: "memory")
#define CPWAIT1()      asm volatile("cp.async.wait_group 1;" ::: "memory")
#define CPWAIT0()      asm volatile("cp.async.wait_group 0;" ::: "memory")

__device__ __forceinline__ void ldsm4(uint32_t* r, uint32_t a) {
    asm volatile("ldmatrix.sync.aligned.m8n8.x4.shared.b16 {%0,%1,%2,%3}, [%4];"
        : "=r"(r[0]), "=r"(r[1]), "=r"(r[2]), "=r"(r[3]) : "r"(a));
}
__device__ __forceinline__ void ldsm4t(uint32_t* r, uint32_t a) {
    asm volatile("ldmatrix.sync.aligned.m8n8.x4.trans.shared.b16 {%0,%1,%2,%3}, [%4];"
        : "=r"(r[0]), "=r"(r[1]), "=r"(r[2]), "=r"(r[3]) : "r"(a));
}
__device__ __forceinline__ void mma_bf16(float* c, const uint32_t* a, const uint32_t* b) {
    asm volatile(
        "mma.sync.aligned.m16n8k16.row.col.f32.bf16.bf16.f32 "
        "{%0,%1,%2,%3}, {%4,%5,%6,%7}, {%8,%9}, {%0,%1,%2,%3};"
        : "+f"(c[0]), "+f"(c[1]), "+f"(c[2]), "+f"(c[3])
        : "r"(a[0]), "r"(a[1]), "r"(a[2]), "r"(a[3]), "r"(b[0]), "r"(b[1]));
}
__device__ __forceinline__ float gelu_exact(float x) {
    return 0.5f * x * (1.0f + erff(x * 0.70710678118654752440f));
}
__device__ __forceinline__ void split2(float v0, float v1,
                                       __nv_bfloat162& h2, __nv_bfloat162& l2) {
    __nv_bfloat16 h0 = __float2bfloat16(v0);
    __nv_bfloat16 h1 = __float2bfloat16(v1);
    __nv_bfloat16 l0 = __float2bfloat16(v0 - __bfloat162float(h0));
    __nv_bfloat16 l1 = __float2bfloat16(v1 - __bfloat162float(h1));
    h2 = __halves2bfloat162(h0, h1);
    l2 = __halves2bfloat162(l0, l1);
}

// ================== split convert: fp32 -> bf16 hi/lo ==================
__global__ __launch_bounds__(256) void split_bf16(
    const float* __restrict__ src, __nv_bfloat16* __restrict__ h,
    __nv_bfloat16* __restrict__ l)
{
    int idx = blockIdx.x * 256 + threadIdx.x;
    float4 v = ((const float4*)src)[idx];
    __nv_bfloat162 h01, l01, h23, l23;
    split2(v.x, v.y, h01, l01);
    split2(v.z, v.w, h23, l23);
    ((__nv_bfloat162*)h)[idx * 2]     = h01;
    ((__nv_bfloat162*)h)[idx * 2 + 1] = h23;
    ((__nv_bfloat162*)l)[idx * 2]     = l01;
    ((__nv_bfloat162*)l)[idx * 2 + 1] = l23;
}

// ================== GEMM: C = A*B + bias, bf16x3 via mma.sync ==================
// A[M,K] bf16 hi/lo row-major, B[K,N] bf16 hi/lo row-major.
// 128x128 tile, 256 threads, warp grid 2(m)x4(n), BK=32, double-buffered cp.async.
// smem stage: A_h[128][40b16] A_l B_h[32][136b16] B_l
#define GM_STAGE 37888
template<int ACT, int WF32, int WSPLIT>
__global__ __launch_bounds__(256) void gemm_bf16x3(
    const __nv_bfloat16* __restrict__ Ah, const __nv_bfloat16* __restrict__ Al,
    const __nv_bfloat16* __restrict__ Bh, const __nv_bfloat16* __restrict__ Bl,
    const float* __restrict__ bias,
    float* __restrict__ Cf, __nv_bfloat16* __restrict__ Ch,
    __nv_bfloat16* __restrict__ Cl, int M, int N, int K)
{
    extern __shared__ char sm[];
    const uint32_t smb = smem_u32(sm);
    const int tid = threadIdx.x, lane = tid & 31, wid = tid >> 5;
    const int warp_m = wid >> 2, warp_n = wid & 3;
    const int bm = blockIdx.y * 128, bn = blockIdx.x * 128;

    float c[4][4][4];
    #pragma unroll
    for (int i = 0; i < 4; i++)
        #pragma unroll
        for (int j = 0; j < 4; j++)
            #pragma unroll
            for (int q = 0; q < 4; q++) c[i][j][q] = 0.f;

    const int rowA  = (lane & 7) + ((lane >> 3) & 1) * 8;
    const int kselA = (lane >> 4) * 8;
    const int kB    = (lane & 7) + ((lane >> 3) & 1) * 8;
    const int nB    = ((lane >> 4) & 1) * 8;

    auto load_stage = [&](int s, int k0) {
        uint32_t base = smb + s * GM_STAGE;
        #pragma unroll
        for (int i = 0; i < 2; i++) {
            int cidx = tid + i * 256;
            int row = cidx >> 2, kc = (cidx & 3) << 3;
            size_t g = (size_t)(bm + row) * K + k0 + kc;
            CP16(base + row * 80 + kc * 2, Ah + g);
            CP16(base + 10240 + row * 80 + kc * 2, Al + g);
        }
        #pragma unroll
        for (int i = 0; i < 2; i++) {
            int cidx = tid + i * 256;
            int k = cidx >> 4, nc = (cidx & 15) << 3;
            size_t g = (size_t)(k0 + k) * N + bn + nc;
            CP16(base + 20480 + k * 272 + nc * 2, Bh + g);
            CP16(base + 29184 + k * 272 + nc * 2, Bl + g);
        }
        CPCOMMIT();
    };

    auto compute = [&](int s) {
        uint32_t bAh = smb + s * GM_STAGE;
        uint32_t bAl = bAh + 10240;
        uint32_t bBh = bAh + 20480;
        uint32_t bBl = bAh + 29184;
        #pragma unroll
        for (int ks = 0; ks < 2; ks++) {
            uint32_t ah[4][4], al[4][4], bh[4][2], bl[4][2];
            #pragma unroll
            for (int mt = 0; mt < 4; mt++) {
                uint32_t off = (uint32_t)((warp_m * 64 + mt * 16 + rowA) * 80 +
                                          (ks * 16 + kselA) * 2);
                ldsm4(ah[mt], bAh + off);
                ldsm4(al[mt], bAl + off);
            }
            #pragma unroll
            for (int ntp = 0; ntp < 2; ntp++) {
                uint32_t off = (uint32_t)((ks * 16 + kB) * 272 +
                                          (warp_n * 32 + ntp * 16 + nB) * 2);
                uint32_t r[4];
                ldsm4t(r, bBh + off);
                bh[2*ntp][0] = r[0]; bh[2*ntp][1] = r[1];
                bh[2*ntp+1][0] = r[2]; bh[2*ntp+1][1] = r[3];
                ldsm4t(r, bBl + off);
                bl[2*ntp][0] = r[0]; bl[2*ntp][1] = r[1];
                bl[2*ntp+1][0] = r[2]; bl[2*ntp+1][1] = r[3];
            }
            #pragma unroll
            for (int mt = 0; mt < 4; mt++)
                #pragma unroll
                for (int nt = 0; nt < 4; nt++) {
                    mma_bf16(c[mt][nt], ah[mt], bh[nt]);
                    mma_bf16(c[mt][nt], ah[mt], bl[nt]);
                    mma_bf16(c[mt][nt], al[mt], bh[nt]);
                }
        }
    };

    const int nt_k = K >> 5;
    load_stage(0, 0);
    for (int t = 0; t < nt_k; t++) {
        if (t + 1 < nt_k) { load_stage((t + 1) & 1, (t + 1) << 5); CPWAIT1(); }
        else              { CPWAIT0(); }
        __syncthreads();
        compute(t & 1);
        __syncthreads();
    }

    // epilogue
    const int g = lane >> 2, tig = lane & 3;
    #pragma unroll
    for (int mt = 0; mt < 4; mt++) {
        #pragma unroll
        for (int nt = 0; nt < 4; nt++) {
            int col = bn + warp_n * 32 + nt * 8 + tig * 2;
            float b0 = bias[col], b1 = bias[col + 1];
            #pragma unroll
            for (int half = 0; half < 2; half++) {
                int row = bm + warp_m * 64 + mt * 16 + g + half * 8;
                float v0 = c[mt][nt][half * 2 + 0] + b0;
                float v1 = c[mt][nt][half * 2 + 1] + b1;
                if (ACT) { v0 = gelu_exact(v0); v1 = gelu_exact(v1); }
                if (WF32)
                    *(float2*)&Cf[(size_t)row * N + col] = make_float2(v0, v1);
                if (WSPLIT) {
                    __nv_bfloat162 h2, l2;
                    split2(v0, v1, h2, l2);
                    *(__nv_bfloat162*)&Ch[(size_t)row * N + col] = h2;
                    *(__nv_bfloat162*)&Cl[(size_t)row * N + col] = l2;
                }
            }
        }
    }
}

// ================== attention scores: S = QK^T*scale + mask ==================
// 128x128 per block, K-dim = 64 (single load). Q,K both [B*S, D] bf16 slices.
// smem: Qh[128][72b16] Ql Kh Kl  (stride 144B)
__global__ __launch_bounds__(256) void attn_scores_mma(
    const __nv_bfloat16* __restrict__ Qh, const __nv_bfloat16* __restrict__ Ql,
    const __nv_bfloat16* __restrict__ Kh, const __nv_bfloat16* __restrict__ Kl,
    const float* __restrict__ mask, float* __restrict__ scores)
{
    extern __shared__ char sm[];
    const uint32_t smb = smem_u32(sm);
    const int tid = threadIdx.x, lane = tid & 31, wid = tid >> 5;
    const int warp_m = wid >> 2, warp_n = wid & 3;
    const int bh = blockIdx.z, b = bh >> 4, h = bh & 15;
    const int si = blockIdx.y * 128, tj = blockIdx.x * 128;

    #pragma unroll
    for (int i = 0; i < 4; i++) {
        int cidx = tid + i * 256;
        int row = cidx >> 3, cc = (cidx & 7) << 3;
        size_t gq = (size_t)(b * SS + si + row) * DD + h * 64 + cc;
        size_t gk = (size_t)(b * SS + tj + row) * DD + h * 64 + cc;
        CP16(smb + 0     + row * 144 + cc * 2, Qh + gq);
        CP16(smb + 18432 + row * 144 + cc * 2, Ql + gq);
        CP16(smb + 36864 + row * 144 + cc * 2, Kh + gk);
        CP16(smb + 55296 + row * 144 + cc * 2, Kl + gk);
    }
    CPCOMMIT(); CPWAIT0();
    __syncthreads();

    float c[4][4][4];
    #pragma unroll
    for (int i = 0; i < 4; i++)
        #pragma unroll
        for (int j = 0; j < 4; j++)
            #pragma unroll
            for (int q = 0; q < 4; q++) c[i][j][q] = 0.f;

    const int rowA  = (lane & 7) + ((lane >> 3) & 1) * 8;
    const int kselA = (lane >> 4) * 8;
    // K operand loaded non-trans (B-frag == A-pattern on K[t][d])
    const int rowK  = (lane & 7) + ((lane >> 4) & 1) * 8;   // t offset within 16
    const int dselK = ((lane >> 3) & 1) * 8;

    #pragma unroll
    for (int ks = 0; ks < 4; ks++) {
        uint32_t ah[4][4], al[4][4], bhreg[4][2], blreg[4][2];
        #pragma unroll
        for (int mt = 0; mt < 4; mt++) {
            uint32_t off = (uint32_t)((warp_m * 64 + mt * 16 + rowA) * 144 +
                                      (ks * 16 + kselA) * 2);
            ldsm4(ah[mt], smb + 0 + off);
            ldsm4(al[mt], smb + 18432 + off);
        }
        #pragma unroll
        for (int ntp = 0; ntp < 2; ntp++) {
            uint32_t off = (uint32_t)((warp_n * 32 + ntp * 16 + rowK) * 144 +
                                      (ks * 16 + dselK) * 2);
            uint32_t r[4];
            ldsm4(r, smb + 36864 + off);
            bhreg[2*ntp][0] = r[0]; bhreg[2*ntp][1] = r[1];
            bhreg[2*ntp+1][0] = r[2]; bhreg[2*ntp+1][1] = r[3];
            ldsm4(r, smb + 55296 + off);
            blreg[2*ntp][0] = r[0]; blreg[2*ntp][1] = r[1];
            blreg[2*ntp+1][0] = r[2]; blreg[2*ntp+1][1] = r[3];
        }
        #pragma unroll
        for (int mt = 0; mt < 4; mt++)
            #pragma unroll
            for (int nt = 0; nt < 4; nt++) {
                mma_bf16(c[mt][nt], ah[mt], bhreg[nt]);
                mma_bf16(c[mt][nt], ah[mt], blreg[nt]);
                mma_bf16(c[mt][nt], al[mt], bhreg[nt]);
            }
    }

    const int g = lane >> 2, tig = lane & 3;
    const float scale = 0.125f;
    #pragma unroll
    for (int mt = 0; mt < 4; mt++) {
        #pragma unroll
        for (int nt = 0; nt < 4; nt++) {
            int col = tj + warp_n * 32 + nt * 8 + tig * 2;
            float m0 = mask[b * SS + col], m1 = mask[b * SS + col + 1];
            #pragma unroll
            for (int half = 0; half < 2; half++) {
                int row = si + warp_m * 64 + mt * 16 + g + half * 8;
                float v0 = c[mt][nt][half * 2 + 0] * scale + m0;
                float v1 = c[mt][nt][half * 2 + 1] * scale + m1;
                *(float2*)&scores[(size_t)bh * SS * SS + (size_t)row * SS + col] =
                    make_float2(v0, v1);
            }
        }
    }
}

// ================== softmax + head_mask -> P bf16 hi/lo ==================
__global__ __launch_bounds__(256) void softmax_hm(
    const float* __restrict__ scores, const float* __restrict__ head_mask,
    int layer, __nv_bfloat16* __restrict__ Ph, __nv_bfloat16* __restrict__ Pl)
{
    const int row  = blockIdx.x * 8 + (threadIdx.x >> 5);
    const int lane = threadIdx.x & 31;
    const int bh   = row >> 10;
    const int h    = bh & (HH - 1);
    const float hm = head_mask[layer * HH + h];

    const float4* p = (const float4*)(scores + (size_t)row * SS);
    float4 v[8];
    float mx = -INFINITY;
    #pragma unroll
    for (int i = 0; i < 8; i++) {
        v[i] = p[lane + i * 32];
        mx = fmaxf(mx, fmaxf(fmaxf(v[i].x, v[i].y), fmaxf(v[i].z, v[i].w)));
    }
    #pragma unroll
    for (int off = 16; off > 0; off >>= 1)
        mx = fmaxf(mx, __shfl_xor_sync(0xffffffffu, mx, off));

    float sum = 0.f;
    #pragma unroll
    for (int i = 0; i < 8; i++) {
        v[i].x = __expf(v[i].x - mx);
        v[i].y = __expf(v[i].y - mx);
        v[i].z = __expf(v[i].z - mx);
        v[i].w = __expf(v[i].w - mx);
        sum += v[i].x + v[i].y + v[i].z + v[i].w;
    }
    #pragma unroll
    for (int off = 16; off > 0; off >>= 1)
        sum += __shfl_xor_sync(0xffffffffu, sum, off);

    const float inv = hm / sum;
    __nv_bfloat162* ph = (__nv_bfloat162*)(Ph + (size_t)row * SS);
    __nv_bfloat162* pl = (__nv_bfloat162*)(Pl + (size_t)row * SS);
    #pragma unroll
    for (int i = 0; i < 8; i++) {
        float v0 = v[i].x * inv, v1 = v[i].y * inv;
        float v2 = v[i].z * inv, v3 = v[i].w * inv;
        __nv_bfloat162 h01, l01, h23, l23;
        split2(v0, v1, h01, l01);
        split2(v2, v3, h23, l23);
        int j = lane + i * 32;
        ph[j * 2] = h01; ph[j * 2 + 1] = h23;
        pl[j * 2] = l01; pl[j * 2 + 1] = l23;
    }
}

// ================== ctx = P V  (128s x 64d per block) ==================
// warp grid 4(m)x2(n); BK=32 over t; double-buffered.
// smem stage: Ph[128][40] Pl  Vh[32][72] Vl
#define CX_STAGE 29696
__global__ __launch_bounds__(256) void attn_ctx_mma(
    const __nv_bfloat16* __restrict__ Ph, const __nv_bfloat16* __restrict__ Pl,
    const __nv_bfloat16* __restrict__ Vh, const __nv_bfloat16* __restrict__ Vl,
    __nv_bfloat16* __restrict__ Ch, __nv_bfloat16* __restrict__ Cl)
{
    extern __shared__ char sm[];
    const uint32_t smb = smem_u32(sm);
    const int tid = threadIdx.x, lane = tid & 31, wid = tid >> 5;
    const int warp_m = wid >> 1, warp_n = wid & 1;
    const int bh = blockIdx.y, b = bh >> 4, h = bh & 15;
    const int si = blockIdx.x * 128;

    float c[2][4][4];
    #pragma unroll
    for (int i = 0; i < 2; i++)
        #pragma unroll
        for (int j = 0; j < 4; j++)
            #pragma unroll
            for (int q = 0; q < 4; q++) c[i][j][q] = 0.f;

    const int rowA  = (lane & 7) + ((lane >> 3) & 1) * 8;
    const int kselA = (lane >> 4) * 8;
    const int kB    = (lane & 7) + ((lane >> 3) & 1) * 8;
    const int nB    = ((lane >> 4) & 1) * 8;

    auto load_stage = [&](int s, int t0) {
        uint32_t base = smb + s * CX_STAGE;
        #pragma unroll
        for (int i = 0; i < 2; i++) {
            int cidx = tid + i * 256;
            int row = cidx >> 2, kc = (cidx & 3) << 3;
            size_t g = (size_t)bh * SS * SS + (size_t)(si + row) * SS + t0 + kc;
            CP16(base + row * 80 + kc * 2, Ph + g);
            CP16(base + 10240 + row * 80 + kc * 2, Pl + g);
        }
        {
            int k = tid >> 3, nc = (tid & 7) << 3;
            size_t g = (size_t)(b * SS + t0 + k) * DD + h * 64 + nc;
            CP16(base + 20480 + k * 144 + nc * 2, Vh + g);
            CP16(base + 25088 + k * 144 + nc * 2, Vl + g);
        }
        CPCOMMIT();
    };

    auto compute = [&](int s) {
        uint32_t bPh = smb + s * CX_STAGE;
        uint32_t bPl = bPh + 10240;
        uint32_t bVh = bPh + 20480;
        uint32_t bVl = bPh + 25088;
        #pragma unroll
        for (int ks = 0; ks < 2; ks++) {
            uint32_t ah[2][4], al[2][4], bhreg[4][2], blreg[4][2];
            #pragma unroll
            for (int mt = 0; mt < 2; mt++) {
                uint32_t off = (uint32_t)((warp_m * 32 + mt * 16 + rowA) * 80 +
                                          (ks * 16 + kselA) * 2);
                ldsm4(ah[mt], bPh + off);
                ldsm4(al[mt], bPl + off);
            }
            #pragma unroll
            for (int ntp = 0; ntp < 2; ntp++) {
                uint32_t off = (uint32_t)((ks * 16 + kB) * 144 +
                                          (warp_n * 32 + ntp * 16 + nB) * 2);
                uint32_t r[4];
                ldsm4t(r, bVh + off);
                bhreg[2*ntp][0] = r[0]; bhreg[2*ntp][1] = r[1];
                bhreg[2*ntp+1][0] = r[2]; bhreg[2*ntp+1][1] = r[3];
                ldsm4t(r, bVl + off);
                blreg[2*ntp][0] = r[0]; blreg[2*ntp][1] = r[1];
                blreg[2*ntp+1][0] = r[2]; blreg[2*ntp+1][1] = r[3];
            }
            #pragma unroll
            for (int mt = 0; mt < 2; mt++)
                #pragma unroll
                for (int nt = 0; nt < 4; nt++) {
                    mma_bf16(c[mt][nt], ah[mt], bhreg[nt]);
                    mma_bf16(c[mt][nt], ah[mt], blreg[nt]);
                    mma_bf16(c[mt][nt], al[mt], bhreg[nt]);
                }
        }
    };

    load_stage(0, 0);
    for (int t = 0; t < SS / 32; t++) {
        if (t + 1 < SS / 32) { load_stage((t + 1) & 1, (t + 1) * 32); CPWAIT1(); }
        else                 { CPWAIT0(); }
        __syncthreads();
        compute(t & 1);
        __syncthreads();
    }

    const int g = lane >> 2, tig = lane & 3;
    #pragma unroll
    for (int mt = 0; mt < 2; mt++) {
        #pragma unroll
        for (int nt = 0; nt < 4; nt++) {
            int col = warp_n * 32 + nt * 8 + tig * 2;
            #pragma unroll
            for (int half = 0; half < 2; half++) {
                int s = si + warp_m * 32 + mt * 16 + g + half * 8;
                float v0 = c[mt][nt][half * 2 + 0];
                float v1 = c[mt][nt][half * 2 + 1];
                __nv_bfloat162 h2, l2;
                split2(v0, v1, h2, l2);
                size_t o = (size_t)(b * SS + s) * DD + h * 64 + col;
                *(__nv_bfloat162*)&Ch[o] = h2;
                *(__nv_bfloat162*)&Cl[o] = l2;
            }
        }
    }
}

// ================== residual + LayerNorm (+ split outputs) ==================
__global__ __launch_bounds__(256) void ln_residual(
    const float* __restrict__ x, const float* __restrict__ y,
    const float* __restrict__ g, const float* __restrict__ b,
    float* __restrict__ out, __nv_bfloat16* __restrict__ oh,
    __nv_bfloat16* __restrict__ ol)
{
    const int row = blockIdx.x;
    const int tid = threadIdx.x;
    const float4* xp = (const float4*)(x + (size_t)row * DD);
    const float4* yp = (const float4*)(y + (size_t)row * DD);

    float4 xv = xp[tid];
    float4 yv = yp[tid];
    float4 s4 = make_float4(xv.x + yv.x, xv.y + yv.y, xv.z + yv.z, xv.w + yv.w);

    float s  = s4.x + s4.y + s4.z + s4.w;
    float ss = s4.x * s4.x + s4.y * s4.y + s4.z * s4.z + s4.w * s4.w;

    const int lane = tid & 31, warp = tid >> 5;
    #pragma unroll
    for (int off = 16; off > 0; off >>= 1) {
        s  += __shfl_xor_sync(0xffffffffu, s, off);
        ss += __shfl_xor_sync(0xffffffffu, ss, off);
    }
    __shared__ float ws[8], wss[8];
    if (lane == 0) { ws[warp] = s; wss[warp] = ss; }
    __syncthreads();
    if (warp == 0) {
        float a  = (lane < 8) ? ws[lane]  : 0.f;
        float aa = (lane < 8) ? wss[lane] : 0.f;
        #pragma unroll
        for (int off = 4; off > 0; off >>= 1) {
            a  += __shfl_xor_sync(0xffffffffu, a, off);
            aa += __shfl_xor_sync(0xffffffffu, aa, off);
        }
        if (lane == 0) { ws[0] = a; wss[0] = aa; }
    }
    __syncthreads();
    const float mean = ws[0] * (1.0f / DD);
    const float var  = wss[0] * (1.0f / DD) - mean * mean;
    const float inv  = rsqrtf(var + 1e-12f);

    const float4 gv = ((const float4*)g)[tid];
    const float4 bv = ((const float4*)b)[tid];
    float4 o;
    o.x = (s4.x - mean) * inv * gv.x + bv.x;
    o.y = (s4.y - mean) * inv * gv.y + bv.y;
    o.z = (s4.z - mean) * inv * gv.z + bv.z;
    o.w = (s4.w - mean) * inv * gv.w + bv.w;
    ((float4*)(out + (size_t)row * DD))[tid] = o;

    __nv_bfloat162 h01, l01, h23, l23;
    split2(o.x, o.y, h01, l01);
    split2(o.z, o.w, h23, l23);
    __nv_bfloat162* hp = (__nv_bfloat162*)(oh + (size_t)row * DD);
    __nv_bfloat162* lp = (__nv_bfloat162*)(ol + (size_t)row * DD);
    hp[tid * 2] = h01; hp[tid * 2 + 1] = h23;
    lp[tid * 2] = l01; lp[tid * 2 + 1] = l23;
}

// ================== host orchestration ==================
extern "C" void kernel_launch(void* const* d_in, const int* in_sizes, int n_in,
                              void* d_out, int out_size)
{
    const float* hidden = (const float*)d_in[0];
    const float* amask  = (const float*)d_in[1];
    const float* hmask  = (const float*)d_in[2];
    const float* q_w    = (const float*)d_in[3];
    const float* q_b    = (const float*)d_in[4];
    const float* k_w    = (const float*)d_in[5];
    const float* k_b    = (const float*)d_in[6];
    const float* v_w    = (const float*)d_in[7];
    const float* v_b    = (const float*)d_in[8];
    const float* o_w    = (const float*)d_in[9];
    const float* o_b    = (const float*)d_in[10];
    const float* aln_g  = (const float*)d_in[11];
    const float* aln_b  = (const float*)d_in[12];
    const float* w1     = (const float*)d_in[13];
    const float* b1     = (const float*)d_in[14];
    const float* w2     = (const float*)d_in[15];
    const float* b2     = (const float*)d_in[16];
    const float* fln_g  = (const float*)d_in[17];
    const float* fln_b  = (const float*)d_in[18];
    float* out = (float*)d_out;

    // resolve scratch
    float *scoresb, *tmpb, *attnb, *hsb;
    __nv_bfloat16 *hs_h, *hs_l, *q_h, *q_l, *k_h, *k_l, *v_h, *v_l;
    __nv_bfloat16 *ctx_h, *ctx_l, *attn_h, *attn_l, *ffn1_h, *ffn1_l, *p_h, *p_l;
    __nv_bfloat16 *wq_h, *wq_l, *wk_h, *wk_l, *wv_h, *wv_l, *wo_h, *wo_l;
    __nv_bfloat16 *w1_h, *w1_l, *w2_h, *w2_l;
    cudaGetSymbolAddress((void**)&scoresb, g_scores);
    cudaGetSymbolAddress((void**)&tmpb,  g_tmp);
    cudaGetSymbolAddress((void**)&attnb, g_attn);
    cudaGetSymbolAddress((void**)&hsb,   g_hs);
    cudaGetSymbolAddress((void**)&hs_h, g_hs_h);  cudaGetSymbolAddress((void**)&hs_l, g_hs_l);
    cudaGetSymbolAddress((void**)&q_h, g_q_h);    cudaGetSymbolAddress((void**)&q_l, g_q_l);
    cudaGetSymbolAddress((void**)&k_h, g_k_h);    cudaGetSymbolAddress((void**)&k_l, g_k_l);
    cudaGetSymbolAddress((void**)&v_h, g_v_h);    cudaGetSymbolAddress((void**)&v_l, g_v_l);
    cudaGetSymbolAddress((void**)&ctx_h, g_ctx_h);   cudaGetSymbolAddress((void**)&ctx_l, g_ctx_l);
    cudaGetSymbolAddress((void**)&attn_h, g_attn_h); cudaGetSymbolAddress((void**)&attn_l, g_attn_l);
    cudaGetSymbolAddress((void**)&ffn1_h, g_ffn1_h); cudaGetSymbolAddress((void**)&ffn1_l, g_ffn1_l);
    cudaGetSymbolAddress((void**)&p_h, g_p_h);    cudaGetSymbolAddress((void**)&p_l, g_p_l);
    cudaGetSymbolAddress((void**)&wq_h, g_wq_h);  cudaGetSymbolAddress((void**)&wq_l, g_wq_l);
    cudaGetSymbolAddress((void**)&wk_h, g_wk_h);  cudaGetSymbolAddress((void**)&wk_l, g_wk_l);
    cudaGetSymbolAddress((void**)&wv_h, g_wv_h);  cudaGetSymbolAddress((void**)&wv_l, g_wv_l);
    cudaGetSymbolAddress((void**)&wo_h, g_wo_h);  cudaGetSymbolAddress((void**)&wo_l, g_wo_l);
    cudaGetSymbolAddress((void**)&w1_h, g_w1_h);  cudaGetSymbolAddress((void**)&w1_l, g_w1_l);
    cudaGetSymbolAddress((void**)&w2_h, g_w2_h);  cudaGetSymbolAddress((void**)&w2_l, g_w2_l);

    cudaFuncSetAttribute(gemm_bf16x3<0,0,1>, cudaFuncAttributeMaxDynamicSharedMemorySize, 2*GM_STAGE);
    cudaFuncSetAttribute(gemm_bf16x3<0,1,0>, cudaFuncAttributeMaxDynamicSharedMemorySize, 2*GM_STAGE);
    cudaFuncSetAttribute(gemm_bf16x3<1,0,1>, cudaFuncAttributeMaxDynamicSharedMemorySize, 2*GM_STAGE);
    cudaFuncSetAttribute(attn_scores_mma, cudaFuncAttributeMaxDynamicSharedMemorySize, 73728);
    cudaFuncSetAttribute(attn_ctx_mma, cudaFuncAttributeMaxDynamicSharedMemorySize, 2*CX_STAGE);

    // weight / input conversion
    split_bf16<<<(DD*DD)/1024, 256>>>(q_w, wq_h, wq_l);
    split_bf16<<<(DD*DD)/1024, 256>>>(k_w, wk_h, wk_l);
    split_bf16<<<(DD*DD)/1024, 256>>>(v_w, wv_h, wv_l);
    split_bf16<<<(DD*DD)/1024, 256>>>(o_w, wo_h, wo_l);
    split_bf16<<<(LL*DD*DFF)/1024, 256>>>(w1, w1_h, w1_l);
    split_bf16<<<(LL*DFF*DD)/1024, 256>>>(w2, w2_h, w2_l);
    split_bf16<<<(MM*DD)/1024, 256>>>(hidden, hs_h, hs_l);

    const dim3 g1(DD/128, MM/128);
    const dim3 g4(DFF/128, MM/128);
    const dim3 sc_grid(SS/128, SS/128, BB*HH);
    const dim3 cx_grid(SS/128, BB*HH);

    for (int l = 0; l < LL; l++) {
        const float* hsin_f = (l == 0) ? hidden : hsb;
        float* hsout = (l == LL - 1) ? out : hsb;

        gemm_bf16x3<0,0,1><<<g1, 256, 2*GM_STAGE>>>(hs_h, hs_l, wq_h, wq_l, q_b,
            nullptr, q_h, q_l, MM, DD, DD);
        gemm_bf16x3<0,0,1><<<g1, 256, 2*GM_STAGE>>>(hs_h, hs_l, wk_h, wk_l, k_b,
            nullptr, k_h, k_l, MM, DD, DD);
        gemm_bf16x3<0,0,1><<<g1, 256, 2*GM_STAGE>>>(hs_h, hs_l, wv_h, wv_l, v_b,
            nullptr, v_h, v_l, MM, DD, DD);

        attn_scores_mma<<<sc_grid, 256, 73728>>>(q_h, q_l, k_h, k_l, amask, scoresb);
        softmax_hm<<<(BB*HH*SS)/8, 256>>>(scoresb, hmask, l, p_h, p_l);
        attn_ctx_mma<<<cx_grid, 256, 2*CX_STAGE>>>(p_h, p_l, v_h, v_l, ctx_h, ctx_l);

        gemm_bf16x3<0,1,0><<<g1, 256, 2*GM_STAGE>>>(ctx_h, ctx_l, wo_h, wo_l, o_b,
            tmpb, nullptr, nullptr, MM, DD, DD);
        ln_residual<<<MM, 256>>>(hsin_f, tmpb, aln_g, aln_b, attnb, attn_h, attn_l);

        gemm_bf16x3<1,0,1><<<g4, 256, 2*GM_STAGE>>>(attn_h, attn_l,
            w1_h + (size_t)l*DD*DFF, w1_l + (size_t)l*DD*DFF, b1 + (size_t)l*DFF,
            nullptr, ffn1_h, ffn1_l, MM, DFF, DD);
        gemm_bf16x3<0,1,0><<<g1, 256, 2*GM_STAGE>>>(ffn1_h, ffn1_l,
            w2_h + (size_t)l*DFF*DD, w2_l + (size_t)l*DFF*DD, b2 + (size_t)l*DD,
            tmpb, nullptr, nullptr, MM, DD, DFF);
        ln_residual<<<MM, 256>>>(attnb, tmpb, fln_g + (size_t)l*DD,
                                 fln_b + (size_t)l*DD, hsout, hs_h, hs_l);
    }
}

// round 5
// speedup vs baseline: 1.0927x; 1.0927x over previous
#include <cuda_runtime.h>
#include <cuda_bf16.h>
#include <math.h>
#include <stdint.h>

// ---------------- problem constants ----------------
#define BB   4
#define SS   1024
#define DD   1024
#define HH   16
#define HDIM 64
#define LL   2
#define DFF  4096
#define MM   (BB*SS)
#define QKVN 3072

// ---------------- static device scratch ----------------
__device__ __align__(256) float g_tmp [(size_t)MM*DD];
__device__ __align__(256) float g_attn[(size_t)MM*DD];
__device__ __align__(256) float g_hs  [(size_t)MM*DD];

__device__ __align__(256) __nv_bfloat16 g_hs_h [(size_t)MM*DD];
__device__ __align__(256) __nv_bfloat16 g_hs_l [(size_t)MM*DD];
__device__ __align__(256) __nv_bfloat16 g_qkv_h[(size_t)MM*QKVN];
__device__ __align__(256) __nv_bfloat16 g_qkv_l[(size_t)MM*QKVN];
__device__ __align__(256) __nv_bfloat16 g_ctx_h[(size_t)MM*DD];
__device__ __align__(256) __nv_bfloat16 g_ctx_l[(size_t)MM*DD];
__device__ __align__(256) __nv_bfloat16 g_attn_h[(size_t)MM*DD];
__device__ __align__(256) __nv_bfloat16 g_attn_l[(size_t)MM*DD];
__device__ __align__(256) __nv_bfloat16 g_ffn1_h[(size_t)MM*DFF];
__device__ __align__(256) __nv_bfloat16 g_ffn1_l[(size_t)MM*DFF];

__device__ __align__(256) __nv_bfloat16 g_wqkv_h[(size_t)DD*QKVN];
__device__ __align__(256) __nv_bfloat16 g_wqkv_l[(size_t)DD*QKVN];
__device__ __align__(256) float         g_bqkv [QKVN];
__device__ __align__(256) __nv_bfloat16 g_wo_h[(size_t)DD*DD];
__device__ __align__(256) __nv_bfloat16 g_wo_l[(size_t)DD*DD];
__device__ __align__(256) __nv_bfloat16 g_w1_h[(size_t)LL*DD*DFF];
__device__ __align__(256) __nv_bfloat16 g_w1_l[(size_t)LL*DD*DFF];
__device__ __align__(256) __nv_bfloat16 g_w2_h[(size_t)LL*DFF*DD];
__device__ __align__(256) __nv_bfloat16 g_w2_l[(size_t)LL*DFF*DD];

// ---------------- asm helpers ----------------
__device__ __forceinline__ uint32_t smem_u32(const void* p) {
    uint32_t a;
    asm("{ .reg .u64 t; cvta.to.shared.u64 t, %1; cvt.u32.u64 %0, t; }"
        : "=r"(a) : "l"(p));
    return a;
}
#define CP16(dst, src) asm volatile("cp.async.cg.shared.global [%0], [%1], 16;" :: "r"(dst), "l"(src) : "memory")
#define CPCOMMIT()     asm volatile("cp.async.commit_group;" ::: "memory")
#define CPWAIT1()      asm volatile("cp.async.wait_group 1;" ::: "memory")
#define CPWAIT0()      asm volatile("cp.async.wait_group 0;" ::: "memory")

__device__ __forceinline__ void ldsm4(uint32_t* r, uint32_t a) {
    asm volatile("ldmatrix.sync.aligned.m8n8.x4.shared.b16 {%0,%1,%2,%3}, [%4];"
        : "=r"(r[0]), "=r"(r[1]), "=r"(r[2]), "=r"(r[3]) : "r"(a));
}
__device__ __forceinline__ void ldsm4t(uint32_t* r, uint32_t a) {
    asm volatile("ldmatrix.sync.aligned.m8n8.x4.trans.shared.b16 {%0,%1,%2,%3}, [%4];"
        : "=r"(r[0]), "=r"(r[1]), "=r"(r[2]), "=r"(r[3]) : "r"(a));
}
__device__ __forceinline__ void mma_bf16(float* c, const uint32_t* a, const uint32_t* b) {
    asm volatile(
        "mma.sync.aligned.m16n8k16.row.col.f32.bf16.bf16.f32 "
        "{%0,%1,%2,%3}, {%4,%5,%6,%7}, {%8,%9}, {%0,%1,%2,%3};"
        : "+f"(c[0]), "+f"(c[1]), "+f"(c[2]), "+f"(c[3])
        : "r"(a[0]), "r"(a[1]), "r"(a[2]), "r"(a[3]), "r"(b[0]), "r"(b[1]));
}
__device__ __forceinline__ float gelu_exact(float x) {
    return 0.5f * x * (1.0f + erff(x * 0.70710678118654752440f));
}
__device__ __forceinline__ void split2(float v0, float v1,
                                       __nv_bfloat162& h2, __nv_bfloat162& l2) {
    __nv_bfloat16 h0 = __float2bfloat16(v0);
    __nv_bfloat16 h1 = __float2bfloat16(v1);
    __nv_bfloat16 l0 = __float2bfloat16(v0 - __bfloat162float(h0));
    __nv_bfloat16 l1 = __float2bfloat16(v1 - __bfloat162float(h1));
    h2 = __halves2bfloat162(h0, h1);
    l2 = __halves2bfloat162(l0, l1);
}
__device__ __forceinline__ uint32_t b2u(__nv_bfloat162 v) {
    return *reinterpret_cast<uint32_t*>(&v);
}

// ================== split convert: fp32 -> bf16 hi/lo ==================
__global__ __launch_bounds__(256) void split_bf16(
    const float* __restrict__ src, __nv_bfloat16* __restrict__ h,
    __nv_bfloat16* __restrict__ l)
{
    int idx = blockIdx.x * 256 + threadIdx.x;
    float4 v = ((const float4*)src)[idx];
    __nv_bfloat162 h01, l01, h23, l23;
    split2(v.x, v.y, h01, l01);
    split2(v.z, v.w, h23, l23);
    ((__nv_bfloat162*)h)[idx * 2]     = h01;
    ((__nv_bfloat162*)h)[idx * 2 + 1] = h23;
    ((__nv_bfloat162*)l)[idx * 2]     = l01;
    ((__nv_bfloat162*)l)[idx * 2 + 1] = l23;
}

// ================== pack QKV weights: [D,3D] hi/lo ==================
__global__ __launch_bounds__(256) void pack_qkv_w(
    const float* __restrict__ q, const float* __restrict__ k,
    const float* __restrict__ v, __nv_bfloat16* __restrict__ h,
    __nv_bfloat16* __restrict__ l)
{
    int i4 = blockIdx.x * 256 + threadIdx.x;   // float4 index over [1024][3072]
    int row = i4 / (QKVN / 4);
    int c   = (i4 % (QKVN / 4)) * 4;
    const float* src = (c < 1024) ? q + (size_t)row * 1024 + c
                     : (c < 2048) ? k + (size_t)row * 1024 + (c - 1024)
                                  : v + (size_t)row * 1024 + (c - 2048);
    float4 vv = *(const float4*)src;
    __nv_bfloat162 h01, l01, h23, l23;
    split2(vv.x, vv.y, h01, l01);
    split2(vv.z, vv.w, h23, l23);
    ((__nv_bfloat162*)h)[i4 * 2]     = h01;
    ((__nv_bfloat162*)h)[i4 * 2 + 1] = h23;
    ((__nv_bfloat162*)l)[i4 * 2]     = l01;
    ((__nv_bfloat162*)l)[i4 * 2 + 1] = l23;
}
__global__ __launch_bounds__(256) void pack_qkv_b(
    const float* __restrict__ q, const float* __restrict__ k,
    const float* __restrict__ v, float* __restrict__ o)
{
    int idx = blockIdx.x * 256 + threadIdx.x;
    o[idx] = (idx < 1024) ? q[idx] : (idx < 2048) ? k[idx - 1024] : v[idx - 2048];
}

// ================== GEMM: C = A*B + bias, bf16x3 via mma.sync ==================
#define GM_STAGE 37888
template<int ACT, int WF32, int WSPLIT>
__global__ __launch_bounds__(256) void gemm_bf16x3(
    const __nv_bfloat16* __restrict__ Ah, const __nv_bfloat16* __restrict__ Al,
    const __nv_bfloat16* __restrict__ Bh, const __nv_bfloat16* __restrict__ Bl,
    const float* __restrict__ bias,
    float* __restrict__ Cf, __nv_bfloat16* __restrict__ Ch,
    __nv_bfloat16* __restrict__ Cl, int M, int N, int K)
{
    extern __shared__ char sm[];
    const uint32_t smb = smem_u32(sm);
    const int tid = threadIdx.x, lane = tid & 31, wid = tid >> 5;
    const int warp_m = wid >> 2, warp_n = wid & 3;
    const int bm = blockIdx.y * 128, bn = blockIdx.x * 128;

    float c[4][4][4];
    #pragma unroll
    for (int i = 0; i < 4; i++)
        #pragma unroll
        for (int j = 0; j < 4; j++)
            #pragma unroll
            for (int q = 0; q < 4; q++) c[i][j][q] = 0.f;

    const int rowA  = (lane & 7) + ((lane >> 3) & 1) * 8;
    const int kselA = (lane >> 4) * 8;
    const int kB    = (lane & 7) + ((lane >> 3) & 1) * 8;
    const int nB    = ((lane >> 4) & 1) * 8;

    auto load_stage = [&](int s, int k0) {
        uint32_t base = smb + s * GM_STAGE;
        #pragma unroll
        for (int i = 0; i < 2; i++) {
            int cidx = tid + i * 256;
            int row = cidx >> 2, kc = (cidx & 3) << 3;
            size_t g = (size_t)(bm + row) * K + k0 + kc;
            CP16(base + row * 80 + kc * 2, Ah + g);
            CP16(base + 10240 + row * 80 + kc * 2, Al + g);
        }
        #pragma unroll
        for (int i = 0; i < 2; i++) {
            int cidx = tid + i * 256;
            int k = cidx >> 4, nc = (cidx & 15) << 3;
            size_t g = (size_t)(k0 + k) * N + bn + nc;
            CP16(base + 20480 + k * 272 + nc * 2, Bh + g);
            CP16(base + 29184 + k * 272 + nc * 2, Bl + g);
        }
        CPCOMMIT();
    };

    auto compute = [&](int s) {
        uint32_t bAh = smb + s * GM_STAGE;
        uint32_t bAl = bAh + 10240;
        uint32_t bBh = bAh + 20480;
        uint32_t bBl = bAh + 29184;
        #pragma unroll
        for (int ks = 0; ks < 2; ks++) {
            uint32_t ah[4][4], al[4][4], bh[4][2], bl[4][2];
            #pragma unroll
            for (int mt = 0; mt < 4; mt++) {
                uint32_t off = (uint32_t)((warp_m * 64 + mt * 16 + rowA) * 80 +
                                          (ks * 16 + kselA) * 2);
                ldsm4(ah[mt], bAh + off);
                ldsm4(al[mt], bAl + off);
            }
            #pragma unroll
            for (int ntp = 0; ntp < 2; ntp++) {
                uint32_t off = (uint32_t)((ks * 16 + kB) * 272 +
                                          (warp_n * 32 + ntp * 16 + nB) * 2);
                uint32_t r[4];
                ldsm4t(r, bBh + off);
                bh[2*ntp][0] = r[0]; bh[2*ntp][1] = r[1];
                bh[2*ntp+1][0] = r[2]; bh[2*ntp+1][1] = r[3];
                ldsm4t(r, bBl + off);
                bl[2*ntp][0] = r[0]; bl[2*ntp][1] = r[1];
                bl[2*ntp+1][0] = r[2]; bl[2*ntp+1][1] = r[3];
            }
            #pragma unroll
            for (int mt = 0; mt < 4; mt++)
                #pragma unroll
                for (int nt = 0; nt < 4; nt++) {
                    mma_bf16(c[mt][nt], ah[mt], bh[nt]);
                    mma_bf16(c[mt][nt], ah[mt], bl[nt]);
                    mma_bf16(c[mt][nt], al[mt], bh[nt]);
                }
        }
    };

    const int nt_k = K >> 5;
    load_stage(0, 0);
    for (int t = 0; t < nt_k; t++) {
        if (t + 1 < nt_k) { load_stage((t + 1) & 1, (t + 1) << 5); CPWAIT1(); }
        else              { CPWAIT0(); }
        __syncthreads();
        compute(t & 1);
        __syncthreads();
    }

    const int g = lane >> 2, tig = lane & 3;
    #pragma unroll
    for (int mt = 0; mt < 4; mt++) {
        #pragma unroll
        for (int nt = 0; nt < 4; nt++) {
            int col = bn + warp_n * 32 + nt * 8 + tig * 2;
            float b0 = bias[col], b1 = bias[col + 1];
            #pragma unroll
            for (int half = 0; half < 2; half++) {
                int row = bm + warp_m * 64 + mt * 16 + g + half * 8;
                float v0 = c[mt][nt][half * 2 + 0] + b0;
                float v1 = c[mt][nt][half * 2 + 1] + b1;
                if (ACT) { v0 = gelu_exact(v0); v1 = gelu_exact(v1); }
                if (WF32)
                    *(float2*)&Cf[(size_t)row * N + col] = make_float2(v0, v1);
                if (WSPLIT) {
                    __nv_bfloat162 h2, l2;
                    split2(v0, v1, h2, l2);
                    *(__nv_bfloat162*)&Ch[(size_t)row * N + col] = h2;
                    *(__nv_bfloat162*)&Cl[(size_t)row * N + col] = l2;
                }
            }
        }
    }
}

// ================== fused flash attention ==================
// grid (S/128, B*H), 256 threads (8 warps), each warp owns 16 query rows.
// Q(128x64 h/l) resident; K/V chunks of 128 keys double-buffered.
// smem: Qh 18432 | Ql 18432 | 2 stages of [Kh|Kl|Vh|Vl] 73728 | mask 4096
#define FA_QH   0
#define FA_QL   18432
#define FA_K(s) (36864 + (s) * 73728)
#define FA_MASK 184320
#define FA_SMEM 188416

__global__ __launch_bounds__(256) void flash_attn(
    const __nv_bfloat16* __restrict__ qkvh, const __nv_bfloat16* __restrict__ qkvl,
    const float* __restrict__ mask, const float* __restrict__ head_mask,
    int layer, __nv_bfloat16* __restrict__ Ch, __nv_bfloat16* __restrict__ Cl)
{
    extern __shared__ char sm[];
    const uint32_t smb = smem_u32(sm);
    const float* sm_mask = (const float*)(sm + FA_MASK);
    const int tid = threadIdx.x, lane = tid & 31, wid = tid >> 5;
    const int bh = blockIdx.y, b = bh >> 4, h = bh & 15;
    const int si = blockIdx.x * 128;
    const float hm = head_mask[layer * HH + h];

    // --- load Q (rows si..si+127, head h) + mask row ---
    #pragma unroll
    for (int i = 0; i < 4; i++) {
        int idx = tid + i * 256;
        int r = idx >> 3, cc = (idx & 7) << 3;
        size_t gq = (size_t)(b * SS + si + r) * QKVN + h * 64 + cc;
        CP16(smb + FA_QH + r * 144 + cc * 2, qkvh + gq);
        CP16(smb + FA_QL + r * 144 + cc * 2, qkvl + gq);
    }
    CP16(smb + FA_MASK + tid * 16, mask + b * SS + tid * 4);

    auto load_kv = [&](int s, int t0) {
        uint32_t base = smb + FA_K(s);
        #pragma unroll
        for (int i = 0; i < 4; i++) {
            int idx = tid + i * 256;
            int r = idx >> 3, cc = (idx & 7) << 3;
            size_t gk = (size_t)(b * SS + t0 + r) * QKVN + 1024 + h * 64 + cc;
            size_t gv = (size_t)(b * SS + t0 + r) * QKVN + 2048 + h * 64 + cc;
            CP16(base + r * 144 + cc * 2, qkvh + gk);
            CP16(base + 18432 + r * 144 + cc * 2, qkvl + gk);
            CP16(base + 36864 + r * 144 + cc * 2, qkvh + gv);
            CP16(base + 55296 + r * 144 + cc * 2, qkvl + gv);
        }
        CPCOMMIT();
    };
    load_kv(0, 0);   // group 0 = Q + mask + KV chunk 0

    const int rowA  = (lane & 7) + ((lane >> 3) & 1) * 8;
    const int kselA = (lane >> 4) * 8;
    const int rowK  = (lane & 7) + ((lane >> 4) & 1) * 8;   // K non-trans B frag
    const int dselK = ((lane >> 3) & 1) * 8;
    const int kB    = (lane & 7) + ((lane >> 3) & 1) * 8;   // V trans B frag
    const int nB    = ((lane >> 4) & 1) * 8;
    const int g = lane >> 2, tig = lane & 3;

    float m_prev0 = -INFINITY, m_prev1 = -INFINITY;
    float l0 = 0.f, l1 = 0.f;
    float acc[8][4];
    #pragma unroll
    for (int i = 0; i < 8; i++)
        #pragma unroll
        for (int q = 0; q < 4; q++) acc[i][q] = 0.f;

    const float scale = 0.125f;

    for (int kc = 0; kc < SS / 128; kc++) {
        const int s = kc & 1;
        if (kc + 1 < SS / 128) { load_kv((kc + 1) & 1, (kc + 1) * 128); CPWAIT1(); }
        else                   { CPWAIT0(); }
        __syncthreads();

        // ---- scores: S[16 x 128] = Q_w · K_chunk^T (bf16x3) ----
        float c[16][4];
        #pragma unroll
        for (int i = 0; i < 16; i++)
            #pragma unroll
            for (int q = 0; q < 4; q++) c[i][q] = 0.f;

        uint32_t kb_h = smb + FA_K(s), kb_l = kb_h + 18432;
        #pragma unroll
        for (int ks = 0; ks < 4; ks++) {
            uint32_t ah[4], al[4];
            uint32_t offa = (uint32_t)((wid * 16 + rowA) * 144 + (ks * 16 + kselA) * 2);
            ldsm4(ah, smb + FA_QH + offa);
            ldsm4(al, smb + FA_QL + offa);
            #pragma unroll
            for (int ntp = 0; ntp < 8; ntp++) {
                uint32_t offb = (uint32_t)((ntp * 16 + rowK) * 144 + (ks * 16 + dselK) * 2);
                uint32_t r4[4];
                ldsm4(r4, kb_h + offb);
                uint32_t bhe[2] = { r4[0], r4[1] }, bho[2] = { r4[2], r4[3] };
                ldsm4(r4, kb_l + offb);
                uint32_t ble[2] = { r4[0], r4[1] }, blo[2] = { r4[2], r4[3] };
                mma_bf16(c[2*ntp],   ah, bhe);
                mma_bf16(c[2*ntp],   ah, ble);
                mma_bf16(c[2*ntp],   al, bhe);
                mma_bf16(c[2*ntp+1], ah, bho);
                mma_bf16(c[2*ntp+1], ah, blo);
                mma_bf16(c[2*ntp+1], al, bho);
            }
        }

        // ---- scale + mask + online softmax ----
        float mx0 = -INFINITY, mx1 = -INFINITY;
        #pragma unroll
        for (int nt = 0; nt < 16; nt++) {
            int col = kc * 128 + nt * 8 + tig * 2;
            float mk0 = sm_mask[col], mk1 = sm_mask[col + 1];
            c[nt][0] = c[nt][0] * scale + mk0;
            c[nt][1] = c[nt][1] * scale + mk1;
            c[nt][2] = c[nt][2] * scale + mk0;
            c[nt][3] = c[nt][3] * scale + mk1;
            mx0 = fmaxf(mx0, fmaxf(c[nt][0], c[nt][1]));
            mx1 = fmaxf(mx1, fmaxf(c[nt][2], c[nt][3]));
        }
        mx0 = fmaxf(mx0, __shfl_xor_sync(0xffffffffu, mx0, 1));
        mx0 = fmaxf(mx0, __shfl_xor_sync(0xffffffffu, mx0, 2));
        mx1 = fmaxf(mx1, __shfl_xor_sync(0xffffffffu, mx1, 1));
        mx1 = fmaxf(mx1, __shfl_xor_sync(0xffffffffu, mx1, 2));

        float mn0 = fmaxf(m_prev0, mx0), mn1 = fmaxf(m_prev1, mx1);
        float al0 = __expf(m_prev0 - mn0), al1 = __expf(m_prev1 - mn1);
        m_prev0 = mn0; m_prev1 = mn1;

        float s0 = 0.f, s1 = 0.f;
        #pragma unroll
        for (int nt = 0; nt < 16; nt++) {
            c[nt][0] = __expf(c[nt][0] - mn0);
            c[nt][1] = __expf(c[nt][1] - mn0);
            c[nt][2] = __expf(c[nt][2] - mn1);
            c[nt][3] = __expf(c[nt][3] - mn1);
            s0 += c[nt][0] + c[nt][1];
            s1 += c[nt][2] + c[nt][3];
        }
        s0 += __shfl_xor_sync(0xffffffffu, s0, 1);
        s0 += __shfl_xor_sync(0xffffffffu, s0, 2);
        s1 += __shfl_xor_sync(0xffffffffu, s1, 1);
        s1 += __shfl_xor_sync(0xffffffffu, s1, 2);
        l0 = l0 * al0 + s0;
        l1 = l1 * al1 + s1;

        #pragma unroll
        for (int d = 0; d < 8; d++) {
            acc[d][0] *= al0; acc[d][1] *= al0;
            acc[d][2] *= al1; acc[d][3] *= al1;
        }

        // ---- P · V (P from C-frags via layout identity; bf16x3) ----
        uint32_t vb_h = smb + FA_K(s) + 36864, vb_l = vb_h + 18432;
        #pragma unroll
        for (int ks2 = 0; ks2 < 8; ks2++) {
            uint32_t pah[4], pal[4];
            __nv_bfloat162 h2, l2;
            split2(c[2*ks2][0],   c[2*ks2][1],   h2, l2); pah[0] = b2u(h2); pal[0] = b2u(l2);
            split2(c[2*ks2][2],   c[2*ks2][3],   h2, l2); pah[1] = b2u(h2); pal[1] = b2u(l2);
            split2(c[2*ks2+1][0], c[2*ks2+1][1], h2, l2); pah[2] = b2u(h2); pal[2] = b2u(l2);
            split2(c[2*ks2+1][2], c[2*ks2+1][3], h2, l2); pah[3] = b2u(h2); pal[3] = b2u(l2);
            #pragma unroll
            for (int ntp2 = 0; ntp2 < 4; ntp2++) {
                uint32_t offv = (uint32_t)((ks2 * 16 + kB) * 144 + (ntp2 * 16 + nB) * 2);
                uint32_t r4[4];
                ldsm4t(r4, vb_h + offv);
                uint32_t vhe[2] = { r4[0], r4[1] }, vho[2] = { r4[2], r4[3] };
                ldsm4t(r4, vb_l + offv);
                uint32_t vle[2] = { r4[0], r4[1] }, vlo[2] = { r4[2], r4[3] };
                mma_bf16(acc[2*ntp2],   pah, vhe);
                mma_bf16(acc[2*ntp2],   pal, vhe);
                mma_bf16(acc[2*ntp2],   pah, vle);
                mma_bf16(acc[2*ntp2+1], pah, vho);
                mma_bf16(acc[2*ntp2+1], pal, vho);
                mma_bf16(acc[2*ntp2+1], pah, vlo);
            }
        }
        __syncthreads();
    }

    // ---- epilogue: ctx = acc * head_mask / l, split to bf16 hi/lo ----
    const float inv0 = hm / l0, inv1 = hm / l1;
    const int row0 = si + wid * 16 + g, row1 = row0 + 8;
    #pragma unroll
    for (int d = 0; d < 8; d++) {
        int col = h * 64 + d * 8 + tig * 2;
        __nv_bfloat162 h2, l2;
        split2(acc[d][0] * inv0, acc[d][1] * inv0, h2, l2);
        size_t o0 = (size_t)(b * SS + row0) * DD + col;
        *(__nv_bfloat162*)&Ch[o0] = h2;
        *(__nv_bfloat162*)&Cl[o0] = l2;
        split2(acc[d][2] * inv1, acc[d][3] * inv1, h2, l2);
        size_t o1 = (size_t)(b * SS + row1) * DD + col;
        *(__nv_bfloat162*)&Ch[o1] = h2;
        *(__nv_bfloat162*)&Cl[o1] = l2;
    }
}

// ================== residual + LayerNorm (+ split outputs) ==================
__global__ __launch_bounds__(256) void ln_residual(
    const float* __restrict__ x, const float* __restrict__ y,
    const float* __restrict__ g, const float* __restrict__ b,
    float* __restrict__ out, __nv_bfloat16* __restrict__ oh,
    __nv_bfloat16* __restrict__ ol)
{
    const int row = blockIdx.x;
    const int tid = threadIdx.x;
    const float4* xp = (const float4*)(x + (size_t)row * DD);
    const float4* yp = (const float4*)(y + (size_t)row * DD);

    float4 xv = xp[tid];
    float4 yv = yp[tid];
    float4 s4 = make_float4(xv.x + yv.x, xv.y + yv.y, xv.z + yv.z, xv.w + yv.w);

    float s  = s4.x + s4.y + s4.z + s4.w;
    float ss = s4.x * s4.x + s4.y * s4.y + s4.z * s4.z + s4.w * s4.w;

    const int lane = tid & 31, warp = tid >> 5;
    #pragma unroll
    for (int off = 16; off > 0; off >>= 1) {
        s  += __shfl_xor_sync(0xffffffffu, s, off);
        ss += __shfl_xor_sync(0xffffffffu, ss, off);
    }
    __shared__ float ws[8], wss[8];
    if (lane == 0) { ws[warp] = s; wss[warp] = ss; }
    __syncthreads();
    if (warp == 0) {
        float a  = (lane < 8) ? ws[lane]  : 0.f;
        float aa = (lane < 8) ? wss[lane] : 0.f;
        #pragma unroll
        for (int off = 4; off > 0; off >>= 1) {
            a  += __shfl_xor_sync(0xffffffffu, a, off);
            aa += __shfl_xor_sync(0xffffffffu, aa, off);
        }
        if (lane == 0) { ws[0] = a; wss[0] = aa; }
    }
    __syncthreads();
    const float mean = ws[0] * (1.0f / DD);
    const float var  = wss[0] * (1.0f / DD) - mean * mean;
    const float inv  = rsqrtf(var + 1e-12f);

    const float4 gv = ((const float4*)g)[tid];
    const float4 bv = ((const float4*)b)[tid];
    float4 o;
    o.x = (s4.x - mean) * inv * gv.x + bv.x;
    o.y = (s4.y - mean) * inv * gv.y + bv.y;
    o.z = (s4.z - mean) * inv * gv.z + bv.z;
    o.w = (s4.w - mean) * inv * gv.w + bv.w;
    ((float4*)(out + (size_t)row * DD))[tid] = o;

    __nv_bfloat162 h01, l01, h23, l23;
    split2(o.x, o.y, h01, l01);
    split2(o.z, o.w, h23, l23);
    __nv_bfloat162* hp = (__nv_bfloat162*)(oh + (size_t)row * DD);
    __nv_bfloat162* lp = (__nv_bfloat162*)(ol + (size_t)row * DD);
    hp[tid * 2] = h01; hp[tid * 2 + 1] = h23;
    lp[tid * 2] = l01; lp[tid * 2 + 1] = l23;
}

// ================== host orchestration ==================
extern "C" void kernel_launch(void* const* d_in, const int* in_sizes, int n_in,
                              void* d_out, int out_size)
{
    const float* hidden = (const float*)d_in[0];
    const float* amask  = (const float*)d_in[1];
    const float* hmask  = (const float*)d_in[2];
    const float* q_w    = (const float*)d_in[3];
    const float* q_b    = (const float*)d_in[4];
    const float* k_w    = (const float*)d_in[5];
    const float* k_b    = (const float*)d_in[6];
    const float* v_w    = (const float*)d_in[7];
    const float* v_b    = (const float*)d_in[8];
    const float* o_w    = (const float*)d_in[9];
    const float* o_b    = (const float*)d_in[10];
    const float* aln_g  = (const float*)d_in[11];
    const float* aln_b  = (const float*)d_in[12];
    const float* w1     = (const float*)d_in[13];
    const float* b1     = (const float*)d_in[14];
    const float* w2     = (const float*)d_in[15];
    const float* b2     = (const float*)d_in[16];
    const float* fln_g  = (const float*)d_in[17];
    const float* fln_b  = (const float*)d_in[18];
    float* out = (float*)d_out;

    float *tmpb, *attnb, *hsb, *bqkvb;
    __nv_bfloat16 *hs_h, *hs_l, *qkv_h, *qkv_l;
    __nv_bfloat16 *ctx_h, *ctx_l, *attn_h, *attn_l, *ffn1_h, *ffn1_l;
    __nv_bfloat16 *wqkv_h, *wqkv_l, *wo_h, *wo_l, *w1_h, *w1_l, *w2_h, *w2_l;
    cudaGetSymbolAddress((void**)&tmpb,  g_tmp);
    cudaGetSymbolAddress((void**)&attnb, g_attn);
    cudaGetSymbolAddress((void**)&hsb,   g_hs);
    cudaGetSymbolAddress((void**)&bqkvb, g_bqkv);
    cudaGetSymbolAddress((void**)&hs_h, g_hs_h);   cudaGetSymbolAddress((void**)&hs_l, g_hs_l);
    cudaGetSymbolAddress((void**)&qkv_h, g_qkv_h); cudaGetSymbolAddress((void**)&qkv_l, g_qkv_l);
    cudaGetSymbolAddress((void**)&ctx_h, g_ctx_h); cudaGetSymbolAddress((void**)&ctx_l, g_ctx_l);
    cudaGetSymbolAddress((void**)&attn_h, g_attn_h); cudaGetSymbolAddress((void**)&attn_l, g_attn_l);
    cudaGetSymbolAddress((void**)&ffn1_h, g_ffn1_h); cudaGetSymbolAddress((void**)&ffn1_l, g_ffn1_l);
    cudaGetSymbolAddress((void**)&wqkv_h, g_wqkv_h); cudaGetSymbolAddress((void**)&wqkv_l, g_wqkv_l);
    cudaGetSymbolAddress((void**)&wo_h, g_wo_h);   cudaGetSymbolAddress((void**)&wo_l, g_wo_l);
    cudaGetSymbolAddress((void**)&w1_h, g_w1_h);   cudaGetSymbolAddress((void**)&w1_l, g_w1_l);
    cudaGetSymbolAddress((void**)&w2_h, g_w2_h);   cudaGetSymbolAddress((void**)&w2_l, g_w2_l);

    cudaFuncSetAttribute(gemm_bf16x3<0,0,1>, cudaFuncAttributeMaxDynamicSharedMemorySize, 2*GM_STAGE);
    cudaFuncSetAttribute(gemm_bf16x3<0,1,0>, cudaFuncAttributeMaxDynamicSharedMemorySize, 2*GM_STAGE);
    cudaFuncSetAttribute(gemm_bf16x3<1,0,1>, cudaFuncAttributeMaxDynamicSharedMemorySize, 2*GM_STAGE);
    cudaFuncSetAttribute(flash_attn, cudaFuncAttributeMaxDynamicSharedMemorySize, FA_SMEM);

    // ---- prep: weight / input conversion ----
    pack_qkv_w<<<(DD*QKVN/4)/256, 256>>>(q_w, k_w, v_w, wqkv_h, wqkv_l);
    pack_qkv_b<<<QKVN/256, 256>>>(q_b, k_b, v_b, bqkvb);
    split_bf16<<<(DD*DD)/1024, 256>>>(o_w, wo_h, wo_l);
    split_bf16<<<(LL*DD*DFF)/1024, 256>>>(w1, w1_h, w1_l);
    split_bf16<<<(LL*DFF*DD)/1024, 256>>>(w2, w2_h, w2_l);
    split_bf16<<<(MM*DD)/1024, 256>>>(hidden, hs_h, hs_l);

    const dim3 g1(DD/128, MM/128);
    const dim3 g4(DFF/128, MM/128);
    const dim3 gqkv(QKVN/128, MM/128);
    const dim3 fa_grid(SS/128, BB*HH);

    for (int l = 0; l < LL; l++) {
        const float* hsin_f = (l == 0) ? hidden : hsb;
        float* hsout = (l == LL - 1) ? out : hsb;

        gemm_bf16x3<0,0,1><<<gqkv, 256, 2*GM_STAGE>>>(hs_h, hs_l, wqkv_h, wqkv_l,
            bqkvb, nullptr, qkv_h, qkv_l, MM, QKVN, DD);

        flash_attn<<<fa_grid, 256, FA_SMEM>>>(qkv_h, qkv_l, amask, hmask, l,
                                              ctx_h, ctx_l);

        gemm_bf16x3<0,1,0><<<g1, 256, 2*GM_STAGE>>>(ctx_h, ctx_l, wo_h, wo_l, o_b,
            tmpb, nullptr, nullptr, MM, DD, DD);
        ln_residual<<<MM, 256>>>(hsin_f, tmpb, aln_g, aln_b, attnb, attn_h, attn_l);

        gemm_bf16x3<1,0,1><<<g4, 256, 2*GM_STAGE>>>(attn_h, attn_l,
            w1_h + (size_t)l*DD*DFF, w1_l + (size_t)l*DD*DFF, b1 + (size_t)l*DFF,
            nullptr, ffn1_h, ffn1_l, MM, DFF, DD);
        gemm_bf16x3<0,1,0><<<g1, 256, 2*GM_STAGE>>>(ffn1_h, ffn1_l,
            w2_h + (size_t)l*DFF*DD, w2_l + (size_t)l*DFF*DD, b2 + (size_t)l*DD,
            tmpb, nullptr, nullptr, MM, DD, DFF);
        ln_residual<<<MM, 256>>>(attnb, tmpb, fln_g + (size_t)l*DD,
                                 fln_b + (size_t)l*DD, hsout, hs_h, hs_l);
    }
}

// round 6
// speedup vs baseline: 1.1064x; 1.0126x over previous
#include <cuda_runtime.h>
#include <cuda_bf16.h>
#include <math.h>
#include <stdint.h>

// ---------------- problem constants ----------------
#define BB   4
#define SS   1024
#define DD   1024
#define HH   16
#define HDIM 64
#define LL   2
#define DFF  4096
#define MM   (BB*SS)
#define QKVN 3072

// ---------------- static device scratch ----------------
__device__ __align__(256) float g_tmp [(size_t)MM*DD];
__device__ __align__(256) float g_attn[(size_t)MM*DD];
__device__ __align__(256) float g_hs  [(size_t)MM*DD];

__device__ __align__(256) __nv_bfloat16 g_hs_h [(size_t)MM*DD];
__device__ __align__(256) __nv_bfloat16 g_hs_l [(size_t)MM*DD];
__device__ __align__(256) __nv_bfloat16 g_qkv_h[(size_t)MM*QKVN];
__device__ __align__(256) __nv_bfloat16 g_qkv_l[(size_t)MM*QKVN];
__device__ __align__(256) __nv_bfloat16 g_ctx_h[(size_t)MM*DD];
__device__ __align__(256) __nv_bfloat16 g_ctx_l[(size_t)MM*DD];
__device__ __align__(256) __nv_bfloat16 g_attn_h[(size_t)MM*DD];
__device__ __align__(256) __nv_bfloat16 g_attn_l[(size_t)MM*DD];
__device__ __align__(256) __nv_bfloat16 g_ffn1_h[(size_t)MM*DFF];
__device__ __align__(256) __nv_bfloat16 g_ffn1_l[(size_t)MM*DFF];

__device__ __align__(256) __nv_bfloat16 g_wqkv_h[(size_t)DD*QKVN];
__device__ __align__(256) __nv_bfloat16 g_wqkv_l[(size_t)DD*QKVN];
__device__ __align__(256) float         g_bqkv [QKVN];
__device__ __align__(256) __nv_bfloat16 g_wo_h[(size_t)DD*DD];
__device__ __align__(256) __nv_bfloat16 g_wo_l[(size_t)DD*DD];
__device__ __align__(256) __nv_bfloat16 g_w1_h[(size_t)LL*DD*DFF];
__device__ __align__(256) __nv_bfloat16 g_w1_l[(size_t)LL*DD*DFF];
__device__ __align__(256) __nv_bfloat16 g_w2_h[(size_t)LL*DFF*DD];
__device__ __align__(256) __nv_bfloat16 g_w2_l[(size_t)LL*DFF*DD];

// ---------------- asm helpers ----------------
__device__ __forceinline__ uint32_t smem_u32(const void* p) {
    uint32_t a;
    asm("{ .reg .u64 t; cvta.to.shared.u64 t, %1; cvt.u32.u64 %0, t; }"
        : "=r"(a) : "l"(p));
    return a;
}
#define CP16(dst, src) asm volatile("cp.async.cg.shared.global [%0], [%1], 16;" :: "r"(dst), "l"(src) : "memory")
#define CPCOMMIT()     asm volatile("cp.async.commit_group;" ::: "memory")
#define CPWAIT1()      asm volatile("cp.async.wait_group 1;" ::: "memory")
#define CPWAIT0()      asm volatile("cp.async.wait_group 0;" ::: "memory")

__device__ __forceinline__ void ldsm4(uint32_t* r, uint32_t a) {
    asm volatile("ldmatrix.sync.aligned.m8n8.x4.shared.b16 {%0,%1,%2,%3}, [%4];"
        : "=r"(r[0]), "=r"(r[1]), "=r"(r[2]), "=r"(r[3]) : "r"(a));
}
__device__ __forceinline__ void ldsm4t(uint32_t* r, uint32_t a) {
    asm volatile("ldmatrix.sync.aligned.m8n8.x4.trans.shared.b16 {%0,%1,%2,%3}, [%4];"
        : "=r"(r[0]), "=r"(r[1]), "=r"(r[2]), "=r"(r[3]) : "r"(a));
}
__device__ __forceinline__ void mma_bf16(float* c, const uint32_t* a, const uint32_t* b) {
    asm volatile(
        "mma.sync.aligned.m16n8k16.row.col.f32.bf16.bf16.f32 "
        "{%0,%1,%2,%3}, {%4,%5,%6,%7}, {%8,%9}, {%0,%1,%2,%3};"
        : "+f"(c[0]), "+f"(c[1]), "+f"(c[2]), "+f"(c[3])
        : "r"(a[0]), "r"(a[1]), "r"(a[2]), "r"(a[3]), "r"(b[0]), "r"(b[1]));
}
__device__ __forceinline__ float gelu_exact(float x) {
    return 0.5f * x * (1.0f + erff(x * 0.70710678118654752440f));
}
__device__ __forceinline__ void split2(float v0, float v1,
                                       __nv_bfloat162& h2, __nv_bfloat162& l2) {
    __nv_bfloat16 h0 = __float2bfloat16(v0);
    __nv_bfloat16 h1 = __float2bfloat16(v1);
    __nv_bfloat16 l0 = __float2bfloat16(v0 - __bfloat162float(h0));
    __nv_bfloat16 l1 = __float2bfloat16(v1 - __bfloat162float(h1));
    h2 = __halves2bfloat162(h0, h1);
    l2 = __halves2bfloat162(l0, l1);
}
__device__ __forceinline__ uint32_t b2u(__nv_bfloat162 v) {
    return *reinterpret_cast<uint32_t*>(&v);
}

// ================== split convert: fp32 -> bf16 hi/lo ==================
__global__ __launch_bounds__(256) void split_bf16(
    const float* __restrict__ src, __nv_bfloat16* __restrict__ h,
    __nv_bfloat16* __restrict__ l)
{
    int idx = blockIdx.x * 256 + threadIdx.x;
    float4 v = ((const float4*)src)[idx];
    __nv_bfloat162 h01, l01, h23, l23;
    split2(v.x, v.y, h01, l01);
    split2(v.z, v.w, h23, l23);
    ((__nv_bfloat162*)h)[idx * 2]     = h01;
    ((__nv_bfloat162*)h)[idx * 2 + 1] = h23;
    ((__nv_bfloat162*)l)[idx * 2]     = l01;
    ((__nv_bfloat162*)l)[idx * 2 + 1] = l23;
}

// ================== pack QKV weights: [D,3D] hi/lo ==================
__global__ __launch_bounds__(256) void pack_qkv_w(
    const float* __restrict__ q, const float* __restrict__ k,
    const float* __restrict__ v, __nv_bfloat16* __restrict__ h,
    __nv_bfloat16* __restrict__ l)
{
    int i4 = blockIdx.x * 256 + threadIdx.x;
    int row = i4 / (QKVN / 4);
    int c   = (i4 % (QKVN / 4)) * 4;
    const float* src = (c < 1024) ? q + (size_t)row * 1024 + c
                     : (c < 2048) ? k + (size_t)row * 1024 + (c - 1024)
                                  : v + (size_t)row * 1024 + (c - 2048);
    float4 vv = *(const float4*)src;
    __nv_bfloat162 h01, l01, h23, l23;
    split2(vv.x, vv.y, h01, l01);
    split2(vv.z, vv.w, h23, l23);
    ((__nv_bfloat162*)h)[i4 * 2]     = h01;
    ((__nv_bfloat162*)h)[i4 * 2 + 1] = h23;
    ((__nv_bfloat162*)l)[i4 * 2]     = l01;
    ((__nv_bfloat162*)l)[i4 * 2 + 1] = l23;
}
__global__ __launch_bounds__(256) void pack_qkv_b(
    const float* __restrict__ q, const float* __restrict__ k,
    const float* __restrict__ v, float* __restrict__ o)
{
    int idx = blockIdx.x * 256 + threadIdx.x;
    o[idx] = (idx < 1024) ? q[idx] : (idx < 2048) ? k[idx - 1024] : v[idx - 2048];
}

// ================== GEMM: C = A*B + bias, bf16x3 via mma.sync ==================
// 128x128 tile, 256 threads, 2(m)x4(n) warps, BK=32, double-buffered cp.async.
// __launch_bounds__(256,2): 2 CTAs/SM (151KB smem, <=128 regs) to hide stalls.
#define GM_STAGE 37888
template<int ACT, int WF32, int WSPLIT>
__global__ __launch_bounds__(256, 2) void gemm_bf16x3(
    const __nv_bfloat16* __restrict__ Ah, const __nv_bfloat16* __restrict__ Al,
    const __nv_bfloat16* __restrict__ Bh, const __nv_bfloat16* __restrict__ Bl,
    const float* __restrict__ bias,
    float* __restrict__ Cf, __nv_bfloat16* __restrict__ Ch,
    __nv_bfloat16* __restrict__ Cl, int M, int N, int K)
{
    extern __shared__ char sm[];
    const uint32_t smb = smem_u32(sm);
    const int tid = threadIdx.x, lane = tid & 31, wid = tid >> 5;
    const int warp_m = wid >> 2, warp_n = wid & 3;
    const int bm = blockIdx.y * 128, bn = blockIdx.x * 128;

    float c[4][4][4];
    #pragma unroll
    for (int i = 0; i < 4; i++)
        #pragma unroll
        for (int j = 0; j < 4; j++)
            #pragma unroll
            for (int q = 0; q < 4; q++) c[i][j][q] = 0.f;

    const int rowA  = (lane & 7) + ((lane >> 3) & 1) * 8;
    const int kselA = (lane >> 4) * 8;
    const int kB    = (lane & 7) + ((lane >> 3) & 1) * 8;
    const int nB    = ((lane >> 4) & 1) * 8;

    auto load_stage = [&](int s, int k0) {
        uint32_t base = smb + s * GM_STAGE;
        #pragma unroll
        for (int i = 0; i < 2; i++) {
            int cidx = tid + i * 256;
            int row = cidx >> 2, kc = (cidx & 3) << 3;
            size_t g = (size_t)(bm + row) * K + k0 + kc;
            CP16(base + row * 80 + kc * 2, Ah + g);
            CP16(base + 10240 + row * 80 + kc * 2, Al + g);
        }
        #pragma unroll
        for (int i = 0; i < 2; i++) {
            int cidx = tid + i * 256;
            int k = cidx >> 4, nc = (cidx & 15) << 3;
            size_t g = (size_t)(k0 + k) * N + bn + nc;
            CP16(base + 20480 + k * 272 + nc * 2, Bh + g);
            CP16(base + 29184 + k * 272 + nc * 2, Bl + g);
        }
        CPCOMMIT();
    };

    auto compute = [&](int s) {
        uint32_t bAh = smb + s * GM_STAGE;
        uint32_t bAl = bAh + 10240;
        uint32_t bBh = bAh + 20480;
        uint32_t bBl = bAh + 29184;
        #pragma unroll
        for (int ks = 0; ks < 2; ks++) {
            uint32_t ah[4][4], al[4][4];
            #pragma unroll
            for (int mt = 0; mt < 4; mt++) {
                uint32_t off = (uint32_t)((warp_m * 64 + mt * 16 + rowA) * 80 +
                                          (ks * 16 + kselA) * 2);
                ldsm4(ah[mt], bAh + off);
                ldsm4(al[mt], bAl + off);
            }
            // B frags loaded per-ntp and consumed immediately (small live range)
            #pragma unroll
            for (int ntp = 0; ntp < 2; ntp++) {
                uint32_t off = (uint32_t)((ks * 16 + kB) * 272 +
                                          (warp_n * 32 + ntp * 16 + nB) * 2);
                uint32_t rh[4], rl[4];
                ldsm4t(rh, bBh + off);
                ldsm4t(rl, bBl + off);
                uint32_t bhe[2] = { rh[0], rh[1] }, bho[2] = { rh[2], rh[3] };
                uint32_t ble[2] = { rl[0], rl[1] }, blo[2] = { rl[2], rl[3] };
                #pragma unroll
                for (int mt = 0; mt < 4; mt++) {
                    mma_bf16(c[mt][2*ntp],   ah[mt], bhe);
                    mma_bf16(c[mt][2*ntp],   ah[mt], ble);
                    mma_bf16(c[mt][2*ntp],   al[mt], bhe);
                    mma_bf16(c[mt][2*ntp+1], ah[mt], bho);
                    mma_bf16(c[mt][2*ntp+1], ah[mt], blo);
                    mma_bf16(c[mt][2*ntp+1], al[mt], bho);
                }
            }
        }
    };

    const int nt_k = K >> 5;
    load_stage(0, 0);
    for (int t = 0; t < nt_k; t++) {
        if (t + 1 < nt_k) { load_stage((t + 1) & 1, (t + 1) << 5); CPWAIT1(); }
        else              { CPWAIT0(); }
        __syncthreads();
        compute(t & 1);
        __syncthreads();
    }

    const int g = lane >> 2, tig = lane & 3;
    #pragma unroll
    for (int mt = 0; mt < 4; mt++) {
        #pragma unroll
        for (int nt = 0; nt < 4; nt++) {
            int col = bn + warp_n * 32 + nt * 8 + tig * 2;
            float b0 = bias[col], b1 = bias[col + 1];
            #pragma unroll
            for (int half = 0; half < 2; half++) {
                int row = bm + warp_m * 64 + mt * 16 + g + half * 8;
                float v0 = c[mt][nt][half * 2 + 0] + b0;
                float v1 = c[mt][nt][half * 2 + 1] + b1;
                if (ACT) { v0 = gelu_exact(v0); v1 = gelu_exact(v1); }
                if (WF32)
                    *(float2*)&Cf[(size_t)row * N + col] = make_float2(v0, v1);
                if (WSPLIT) {
                    __nv_bfloat162 h2, l2;
                    split2(v0, v1, h2, l2);
                    *(__nv_bfloat162*)&Ch[(size_t)row * N + col] = h2;
                    *(__nv_bfloat162*)&Cl[(size_t)row * N + col] = l2;
                }
            }
        }
    }
}

// ================== fused flash attention ==================
#define FA_QH   0
#define FA_QL   18432
#define FA_K(s) (36864 + (s) * 73728)
#define FA_MASK 184320
#define FA_SMEM 188416

__global__ __launch_bounds__(256) void flash_attn(
    const __nv_bfloat16* __restrict__ qkvh, const __nv_bfloat16* __restrict__ qkvl,
    const float* __restrict__ mask, const float* __restrict__ head_mask,
    int layer, __nv_bfloat16* __restrict__ Ch, __nv_bfloat16* __restrict__ Cl)
{
    extern __shared__ char sm[];
    const uint32_t smb = smem_u32(sm);
    const float* sm_mask = (const float*)(sm + FA_MASK);
    const int tid = threadIdx.x, lane = tid & 31, wid = tid >> 5;
    const int bh = blockIdx.y, b = bh >> 4, h = bh & 15;
    const int si = blockIdx.x * 128;
    const float hm = head_mask[layer * HH + h];

    #pragma unroll
    for (int i = 0; i < 4; i++) {
        int idx = tid + i * 256;
        int r = idx >> 3, cc = (idx & 7) << 3;
        size_t gq = (size_t)(b * SS + si + r) * QKVN + h * 64 + cc;
        CP16(smb + FA_QH + r * 144 + cc * 2, qkvh + gq);
        CP16(smb + FA_QL + r * 144 + cc * 2, qkvl + gq);
    }
    CP16(smb + FA_MASK + tid * 16, mask + b * SS + tid * 4);

    auto load_kv = [&](int s, int t0) {
        uint32_t base = smb + FA_K(s);
        #pragma unroll
        for (int i = 0; i < 4; i++) {
            int idx = tid + i * 256;
            int r = idx >> 3, cc = (idx & 7) << 3;
            size_t gk = (size_t)(b * SS + t0 + r) * QKVN + 1024 + h * 64 + cc;
            size_t gv = (size_t)(b * SS + t0 + r) * QKVN + 2048 + h * 64 + cc;
            CP16(base + r * 144 + cc * 2, qkvh + gk);
            CP16(base + 18432 + r * 144 + cc * 2, qkvl + gk);
            CP16(base + 36864 + r * 144 + cc * 2, qkvh + gv);
            CP16(base + 55296 + r * 144 + cc * 2, qkvl + gv);
        }
        CPCOMMIT();
    };
    load_kv(0, 0);

    const int rowA  = (lane & 7) + ((lane >> 3) & 1) * 8;
    const int kselA = (lane >> 4) * 8;
    const int rowK  = (lane & 7) + ((lane >> 4) & 1) * 8;
    const int dselK = ((lane >> 3) & 1) * 8;
    const int kB    = (lane & 7) + ((lane >> 3) & 1) * 8;
    const int nB    = ((lane >> 4) & 1) * 8;
    const int g = lane >> 2, tig = lane & 3;

    float m_prev0 = -INFINITY, m_prev1 = -INFINITY;
    float l0 = 0.f, l1 = 0.f;
    float acc[8][4];
    #pragma unroll
    for (int i = 0; i < 8; i++)
        #pragma unroll
        for (int q = 0; q < 4; q++) acc[i][q] = 0.f;

    const float scale = 0.125f;

    for (int kc = 0; kc < SS / 128; kc++) {
        const int s = kc & 1;
        if (kc + 1 < SS / 128) { load_kv((kc + 1) & 1, (kc + 1) * 128); CPWAIT1(); }
        else                   { CPWAIT0(); }
        __syncthreads();

        float c[16][4];
        #pragma unroll
        for (int i = 0; i < 16; i++)
            #pragma unroll
            for (int q = 0; q < 4; q++) c[i][q] = 0.f;

        uint32_t kb_h = smb + FA_K(s), kb_l = kb_h + 18432;
        #pragma unroll
        for (int ks = 0; ks < 4; ks++) {
            uint32_t ah[4], al[4];
            uint32_t offa = (uint32_t)((wid * 16 + rowA) * 144 + (ks * 16 + kselA) * 2);
            ldsm4(ah, smb + FA_QH + offa);
            ldsm4(al, smb + FA_QL + offa);
            #pragma unroll
            for (int ntp = 0; ntp < 8; ntp++) {
                uint32_t offb = (uint32_t)((ntp * 16 + rowK) * 144 + (ks * 16 + dselK) * 2);
                uint32_t r4[4];
                ldsm4(r4, kb_h + offb);
                uint32_t bhe[2] = { r4[0], r4[1] }, bho[2] = { r4[2], r4[3] };
                ldsm4(r4, kb_l + offb);
                uint32_t ble[2] = { r4[0], r4[1] }, blo[2] = { r4[2], r4[3] };
                mma_bf16(c[2*ntp],   ah, bhe);
                mma_bf16(c[2*ntp],   ah, ble);
                mma_bf16(c[2*ntp],   al, bhe);
                mma_bf16(c[2*ntp+1], ah, bho);
                mma_bf16(c[2*ntp+1], ah, blo);
                mma_bf16(c[2*ntp+1], al, bho);
            }
        }

        float mx0 = -INFINITY, mx1 = -INFINITY;
        #pragma unroll
        for (int nt = 0; nt < 16; nt++) {
            int col = kc * 128 + nt * 8 + tig * 2;
            float mk0 = sm_mask[col], mk1 = sm_mask[col + 1];
            c[nt][0] = c[nt][0] * scale + mk0;
            c[nt][1] = c[nt][1] * scale + mk1;
            c[nt][2] = c[nt][2] * scale + mk0;
            c[nt][3] = c[nt][3] * scale + mk1;
            mx0 = fmaxf(mx0, fmaxf(c[nt][0], c[nt][1]));
            mx1 = fmaxf(mx1, fmaxf(c[nt][2], c[nt][3]));
        }
        mx0 = fmaxf(mx0, __shfl_xor_sync(0xffffffffu, mx0, 1));
        mx0 = fmaxf(mx0, __shfl_xor_sync(0xffffffffu, mx0, 2));
        mx1 = fmaxf(mx1, __shfl_xor_sync(0xffffffffu, mx1, 1));
        mx1 = fmaxf(mx1, __shfl_xor_sync(0xffffffffu, mx1, 2));

        float mn0 = fmaxf(m_prev0, mx0), mn1 = fmaxf(m_prev1, mx1);
        float al0 = __expf(m_prev0 - mn0), al1 = __expf(m_prev1 - mn1);
        m_prev0 = mn0; m_prev1 = mn1;

        float s0 = 0.f, s1 = 0.f;
        #pragma unroll
        for (int nt = 0; nt < 16; nt++) {
            c[nt][0] = __expf(c[nt][0] - mn0);
            c[nt][1] = __expf(c[nt][1] - mn0);
            c[nt][2] = __expf(c[nt][2] - mn1);
            c[nt][3] = __expf(c[nt][3] - mn1);
            s0 += c[nt][0] + c[nt][1];
            s1 += c[nt][2] + c[nt][3];
        }
        s0 += __shfl_xor_sync(0xffffffffu, s0, 1);
        s0 += __shfl_xor_sync(0xffffffffu, s0, 2);
        s1 += __shfl_xor_sync(0xffffffffu, s1, 1);
        s1 += __shfl_xor_sync(0xffffffffu, s1, 2);
        l0 = l0 * al0 + s0;
        l1 = l1 * al1 + s1;

        #pragma unroll
        for (int d = 0; d < 8; d++) {
            acc[d][0] *= al0; acc[d][1] *= al0;
            acc[d][2] *= al1; acc[d][3] *= al1;
        }

        uint32_t vb_h = smb + FA_K(s) + 36864, vb_l = vb_h + 18432;
        #pragma unroll
        for (int ks2 = 0; ks2 < 8; ks2++) {
            uint32_t pah[4], pal[4];
            __nv_bfloat162 h2, l2;
            split2(c[2*ks2][0],   c[2*ks2][1],   h2, l2); pah[0] = b2u(h2); pal[0] = b2u(l2);
            split2(c[2*ks2][2],   c[2*ks2][3],   h2, l2); pah[1] = b2u(h2); pal[1] = b2u(l2);
            split2(c[2*ks2+1][0], c[2*ks2+1][1], h2, l2); pah[2] = b2u(h2); pal[2] = b2u(l2);
            split2(c[2*ks2+1][2], c[2*ks2+1][3], h2, l2); pah[3] = b2u(h2); pal[3] = b2u(l2);
            #pragma unroll
            for (int ntp2 = 0; ntp2 < 4; ntp2++) {
                uint32_t offv = (uint32_t)((ks2 * 16 + kB) * 144 + (ntp2 * 16 + nB) * 2);
                uint32_t r4[4];
                ldsm4t(r4, vb_h + offv);
                uint32_t vhe[2] = { r4[0], r4[1] }, vho[2] = { r4[2], r4[3] };
                ldsm4t(r4, vb_l + offv);
                uint32_t vle[2] = { r4[0], r4[1] }, vlo[2] = { r4[2], r4[3] };
                mma_bf16(acc[2*ntp2],   pah, vhe);
                mma_bf16(acc[2*ntp2],   pal, vhe);
                mma_bf16(acc[2*ntp2],   pah, vle);
                mma_bf16(acc[2*ntp2+1], pah, vho);
                mma_bf16(acc[2*ntp2+1], pal, vho);
                mma_bf16(acc[2*ntp2+1], pah, vlo);
            }
        }
        __syncthreads();
    }

    const float inv0 = hm / l0, inv1 = hm / l1;
    const int row0 = si + wid * 16 + g, row1 = row0 + 8;
    #pragma unroll
    for (int d = 0; d < 8; d++) {
        int col = h * 64 + d * 8 + tig * 2;
        __nv_bfloat162 h2, l2;
        split2(acc[d][0] * inv0, acc[d][1] * inv0, h2, l2);
        size_t o0 = (size_t)(b * SS + row0) * DD + col;
        *(__nv_bfloat162*)&Ch[o0] = h2;
        *(__nv_bfloat162*)&Cl[o0] = l2;
        split2(acc[d][2] * inv1, acc[d][3] * inv1, h2, l2);
        size_t o1 = (size_t)(b * SS + row1) * DD + col;
        *(__nv_bfloat162*)&Ch[o1] = h2;
        *(__nv_bfloat162*)&Cl[o1] = l2;
    }
}

// ================== residual + LayerNorm (+ split outputs) ==================
__global__ __launch_bounds__(256) void ln_residual(
    const float* __restrict__ x, const float* __restrict__ y,
    const float* __restrict__ g, const float* __restrict__ b,
    float* __restrict__ out, __nv_bfloat16* __restrict__ oh,
    __nv_bfloat16* __restrict__ ol)
{
    const int row = blockIdx.x;
    const int tid = threadIdx.x;
    const float4* xp = (const float4*)(x + (size_t)row * DD);
    const float4* yp = (const float4*)(y + (size_t)row * DD);

    float4 xv = xp[tid];
    float4 yv = yp[tid];
    float4 s4 = make_float4(xv.x + yv.x, xv.y + yv.y, xv.z + yv.z, xv.w + yv.w);

    float s  = s4.x + s4.y + s4.z + s4.w;
    float ss = s4.x * s4.x + s4.y * s4.y + s4.z * s4.z + s4.w * s4.w;

    const int lane = tid & 31, warp = tid >> 5;
    #pragma unroll
    for (int off = 16; off > 0; off >>= 1) {
        s  += __shfl_xor_sync(0xffffffffu, s, off);
        ss += __shfl_xor_sync(0xffffffffu, ss, off);
    }
    __shared__ float ws[8], wss[8];
    if (lane == 0) { ws[warp] = s; wss[warp] = ss; }
    __syncthreads();
    if (warp == 0) {
        float a  = (lane < 8) ? ws[lane]  : 0.f;
        float aa = (lane < 8) ? wss[lane] : 0.f;
        #pragma unroll
        for (int off = 4; off > 0; off >>= 1) {
            a  += __shfl_xor_sync(0xffffffffu, a, off);
            aa += __shfl_xor_sync(0xffffffffu, aa, off);
        }
        if (lane == 0) { ws[0] = a; wss[0] = aa; }
    }
    __syncthreads();
    const float mean = ws[0] * (1.0f / DD);
    const float var  = wss[0] * (1.0f / DD) - mean * mean;
    const float inv  = rsqrtf(var + 1e-12f);

    const float4 gv = ((const float4*)g)[tid];
    const float4 bv = ((const float4*)b)[tid];
    float4 o;
    o.x = (s4.x - mean) * inv * gv.x + bv.x;
    o.y = (s4.y - mean) * inv * gv.y + bv.y;
    o.z = (s4.z - mean) * inv * gv.z + bv.z;
    o.w = (s4.w - mean) * inv * gv.w + bv.w;
    ((float4*)(out + (size_t)row * DD))[tid] = o;

    __nv_bfloat162 h01, l01, h23, l23;
    split2(o.x, o.y, h01, l01);
    split2(o.z, o.w, h23, l23);
    __nv_bfloat162* hp = (__nv_bfloat162*)(oh + (size_t)row * DD);
    __nv_bfloat162* lp = (__nv_bfloat162*)(ol + (size_t)row * DD);
    hp[tid * 2] = h01; hp[tid * 2 + 1] = h23;
    lp[tid * 2] = l01; lp[tid * 2 + 1] = l23;
}

// ================== host orchestration ==================
extern "C" void kernel_launch(void* const* d_in, const int* in_sizes, int n_in,
                              void* d_out, int out_size)
{
    const float* hidden = (const float*)d_in[0];
    const float* amask  = (const float*)d_in[1];
    const float* hmask  = (const float*)d_in[2];
    const float* q_w    = (const float*)d_in[3];
    const float* q_b    = (const float*)d_in[4];
    const float* k_w    = (const float*)d_in[5];
    const float* k_b    = (const float*)d_in[6];
    const float* v_w    = (const float*)d_in[7];
    const float* v_b    = (const float*)d_in[8];
    const float* o_w    = (const float*)d_in[9];
    const float* o_b    = (const float*)d_in[10];
    const float* aln_g  = (const float*)d_in[11];
    const float* aln_b  = (const float*)d_in[12];
    const float* w1     = (const float*)d_in[13];
    const float* b1     = (const float*)d_in[14];
    const float* w2     = (const float*)d_in[15];
    const float* b2     = (const float*)d_in[16];
    const float* fln_g  = (const float*)d_in[17];
    const float* fln_b  = (const float*)d_in[18];
    float* out = (float*)d_out;

    float *tmpb, *attnb, *hsb, *bqkvb;
    __nv_bfloat16 *hs_h, *hs_l, *qkv_h, *qkv_l;
    __nv_bfloat16 *ctx_h, *ctx_l, *attn_h, *attn_l, *ffn1_h, *ffn1_l;
    __nv_bfloat16 *wqkv_h, *wqkv_l, *wo_h, *wo_l, *w1_h, *w1_l, *w2_h, *w2_l;
    cudaGetSymbolAddress((void**)&tmpb,  g_tmp);
    cudaGetSymbolAddress((void**)&attnb, g_attn);
    cudaGetSymbolAddress((void**)&hsb,   g_hs);
    cudaGetSymbolAddress((void**)&bqkvb, g_bqkv);
    cudaGetSymbolAddress((void**)&hs_h, g_hs_h);   cudaGetSymbolAddress((void**)&hs_l, g_hs_l);
    cudaGetSymbolAddress((void**)&qkv_h, g_qkv_h); cudaGetSymbolAddress((void**)&qkv_l, g_qkv_l);
    cudaGetSymbolAddress((void**)&ctx_h, g_ctx_h); cudaGetSymbolAddress((void**)&ctx_l, g_ctx_l);
    cudaGetSymbolAddress((void**)&attn_h, g_attn_h); cudaGetSymbolAddress((void**)&attn_l, g_attn_l);
    cudaGetSymbolAddress((void**)&ffn1_h, g_ffn1_h); cudaGetSymbolAddress((void**)&ffn1_l, g_ffn1_l);
    cudaGetSymbolAddress((void**)&wqkv_h, g_wqkv_h); cudaGetSymbolAddress((void**)&wqkv_l, g_wqkv_l);
    cudaGetSymbolAddress((void**)&wo_h, g_wo_h);   cudaGetSymbolAddress((void**)&wo_l, g_wo_l);
    cudaGetSymbolAddress((void**)&w1_h, g_w1_h);   cudaGetSymbolAddress((void**)&w1_l, g_w1_l);
    cudaGetSymbolAddress((void**)&w2_h, g_w2_h);   cudaGetSymbolAddress((void**)&w2_l, g_w2_l);

    cudaFuncSetAttribute(gemm_bf16x3<0,0,1>, cudaFuncAttributeMaxDynamicSharedMemorySize, 2*GM_STAGE);
    cudaFuncSetAttribute(gemm_bf16x3<0,1,0>, cudaFuncAttributeMaxDynamicSharedMemorySize, 2*GM_STAGE);
    cudaFuncSetAttribute(gemm_bf16x3<1,0,1>, cudaFuncAttributeMaxDynamicSharedMemorySize, 2*GM_STAGE);
    cudaFuncSetAttribute(flash_attn, cudaFuncAttributeMaxDynamicSharedMemorySize, FA_SMEM);

    pack_qkv_w<<<(DD*QKVN/4)/256, 256>>>(q_w, k_w, v_w, wqkv_h, wqkv_l);
    pack_qkv_b<<<QKVN/256, 256>>>(q_b, k_b, v_b, bqkvb);
    split_bf16<<<(DD*DD)/1024, 256>>>(o_w, wo_h, wo_l);
    split_bf16<<<(LL*DD*DFF)/1024, 256>>>(w1, w1_h, w1_l);
    split_bf16<<<(LL*DFF*DD)/1024, 256>>>(w2, w2_h, w2_l);
    split_bf16<<<(MM*DD)/1024, 256>>>(hidden, hs_h, hs_l);

    const dim3 g1(DD/128, MM/128);
    const dim3 g4(DFF/128, MM/128);
    const dim3 gqkv(QKVN/128, MM/128);
    const dim3 fa_grid(SS/128, BB*HH);

    for (int l = 0; l < LL; l++) {
        const float* hsin_f = (l == 0) ? hidden : hsb;
        float* hsout = (l == LL - 1) ? out : hsb;

        gemm_bf16x3<0,0,1><<<gqkv, 256, 2*GM_STAGE>>>(hs_h, hs_l, wqkv_h, wqkv_l,
            bqkvb, nullptr, qkv_h, qkv_l, MM, QKVN, DD);

        flash_attn<<<fa_grid, 256, FA_SMEM>>>(qkv_h, qkv_l, amask, hmask, l,
                                              ctx_h, ctx_l);

        gemm_bf16x3<0,1,0><<<g1, 256, 2*GM_STAGE>>>(ctx_h, ctx_l, wo_h, wo_l, o_b,
            tmpb, nullptr, nullptr, MM, DD, DD);
        ln_residual<<<MM, 256>>>(hsin_f, tmpb, aln_g, aln_b, attnb, attn_h, attn_l);

        gemm_bf16x3<1,0,1><<<g4, 256, 2*GM_STAGE>>>(attn_h, attn_l,
            w1_h + (size_t)l*DD*DFF, w1_l + (size_t)l*DD*DFF, b1 + (size_t)l*DFF,
            nullptr, ffn1_h, ffn1_l, MM, DFF, DD);
        gemm_bf16x3<0,1,0><<<g1, 256, 2*GM_STAGE>>>(ffn1_h, ffn1_l,
            w2_h + (size_t)l*DFF*DD, w2_l + (size_t)l*DFF*DD, b2 + (size_t)l*DD,
            tmpb, nullptr, nullptr, MM, DD, DFF);
        ln_residual<<<MM, 256>>>(attnb, tmpb, fln_g + (size_t)l*DD,
                                 fln_b + (size_t)l*DD, hsout, hs_h, hs_l);
    }
}

// round 7
// speedup vs baseline: 1.1203x; 1.0125x over previous
#include <cuda_runtime.h>
#include <cuda_bf16.h>
#include <math.h>
#include <stdint.h>

// ---------------- problem constants ----------------
#define BB   4
#define SS   1024
#define DD   1024
#define HH   16
#define HDIM 64
#define LL   2
#define DFF  4096
#define MM   (BB*SS)
#define QKVN 3072

// ---------------- static device scratch ----------------
__device__ __align__(256) float g_tmp [(size_t)MM*DD];
__device__ __align__(256) float g_attn[(size_t)MM*DD];
__device__ __align__(256) float g_hs  [(size_t)MM*DD];

__device__ __align__(256) __nv_bfloat16 g_hs_h [(size_t)MM*DD];
__device__ __align__(256) __nv_bfloat16 g_hs_l [(size_t)MM*DD];
__device__ __align__(256) __nv_bfloat16 g_qkv_h[(size_t)MM*QKVN];
__device__ __align__(256) __nv_bfloat16 g_qkv_l[(size_t)MM*QKVN];
__device__ __align__(256) __nv_bfloat16 g_ctx_h[(size_t)MM*DD];
__device__ __align__(256) __nv_bfloat16 g_ctx_l[(size_t)MM*DD];
__device__ __align__(256) __nv_bfloat16 g_attn_h[(size_t)MM*DD];
__device__ __align__(256) __nv_bfloat16 g_attn_l[(size_t)MM*DD];
__device__ __align__(256) __nv_bfloat16 g_ffn1_h[(size_t)MM*DFF];
__device__ __align__(256) __nv_bfloat16 g_ffn1_l[(size_t)MM*DFF];

__device__ __align__(256) __nv_bfloat16 g_wqkv_h[(size_t)DD*QKVN];
__device__ __align__(256) __nv_bfloat16 g_wqkv_l[(size_t)DD*QKVN];
__device__ __align__(256) float         g_bqkv [QKVN];
__device__ __align__(256) __nv_bfloat16 g_wo_h[(size_t)DD*DD];
__device__ __align__(256) __nv_bfloat16 g_wo_l[(size_t)DD*DD];
__device__ __align__(256) __nv_bfloat16 g_w1_h[(size_t)LL*DD*DFF];
__device__ __align__(256) __nv_bfloat16 g_w1_l[(size_t)LL*DD*DFF];
__device__ __align__(256) __nv_bfloat16 g_w2_h[(size_t)LL*DFF*DD];
__device__ __align__(256) __nv_bfloat16 g_w2_l[(size_t)LL*DFF*DD];

// ---------------- asm helpers ----------------
__device__ __forceinline__ uint32_t smem_u32(const void* p) {
    uint32_t a;
    asm("{ .reg .u64 t; cvta.to.shared.u64 t, %1; cvt.u32.u64 %0, t; }"
        : "=r"(a) : "l"(p));
    return a;
}
#define CP16(dst, src) asm volatile("cp.async.cg.shared.global [%0], [%1], 16;" :: "r"(dst), "l"(src) : "memory")
#define CPCOMMIT()     asm volatile("cp.async.commit_group;" ::: "memory")
#define CPWAIT1()      asm volatile("cp.async.wait_group 1;" ::: "memory")
#define CPWAIT0()      asm volatile("cp.async.wait_group 0;" ::: "memory")

__device__ __forceinline__ void ldsm4(uint32_t* r, uint32_t a) {
    asm volatile("ldmatrix.sync.aligned.m8n8.x4.shared.b16 {%0,%1,%2,%3}, [%4];"
        : "=r"(r[0]), "=r"(r[1]), "=r"(r[2]), "=r"(r[3]) : "r"(a));
}
__device__ __forceinline__ void ldsm4t(uint32_t* r, uint32_t a) {
    asm volatile("ldmatrix.sync.aligned.m8n8.x4.trans.shared.b16 {%0,%1,%2,%3}, [%4];"
        : "=r"(r[0]), "=r"(r[1]), "=r"(r[2]), "=r"(r[3]) : "r"(a));
}
__device__ __forceinline__ void mma_bf16(float* c, const uint32_t* a, const uint32_t* b) {
    asm volatile(
        "mma.sync.aligned.m16n8k16.row.col.f32.bf16.bf16.f32 "
        "{%0,%1,%2,%3}, {%4,%5,%6,%7}, {%8,%9}, {%0,%1,%2,%3};"
        : "+f"(c[0]), "+f"(c[1]), "+f"(c[2]), "+f"(c[3])
        : "r"(a[0]), "r"(a[1]), "r"(a[2]), "r"(a[3]), "r"(b[0]), "r"(b[1]));
}
__device__ __forceinline__ float gelu_exact(float x) {
    return 0.5f * x * (1.0f + erff(x * 0.70710678118654752440f));
}
__device__ __forceinline__ void split2(float v0, float v1,
                                       __nv_bfloat162& h2, __nv_bfloat162& l2) {
    __nv_bfloat16 h0 = __float2bfloat16(v0);
    __nv_bfloat16 h1 = __float2bfloat16(v1);
    __nv_bfloat16 l0 = __float2bfloat16(v0 - __bfloat162float(h0));
    __nv_bfloat16 l1 = __float2bfloat16(v1 - __bfloat162float(h1));
    h2 = __halves2bfloat162(h0, h1);
    l2 = __halves2bfloat162(l0, l1);
}
__device__ __forceinline__ uint32_t b2u(__nv_bfloat162 v) {
    return *reinterpret_cast<uint32_t*>(&v);
}

// ================== split convert: fp32 -> bf16 hi/lo ==================
__global__ __launch_bounds__(256) void split_bf16(
    const float* __restrict__ src, __nv_bfloat16* __restrict__ h,
    __nv_bfloat16* __restrict__ l)
{
    int idx = blockIdx.x * 256 + threadIdx.x;
    float4 v = ((const float4*)src)[idx];
    __nv_bfloat162 h01, l01, h23, l23;
    split2(v.x, v.y, h01, l01);
    split2(v.z, v.w, h23, l23);
    ((__nv_bfloat162*)h)[idx * 2]     = h01;
    ((__nv_bfloat162*)h)[idx * 2 + 1] = h23;
    ((__nv_bfloat162*)l)[idx * 2]     = l01;
    ((__nv_bfloat162*)l)[idx * 2 + 1] = l23;
}

// ================== pack QKV weights: [D,3D] hi/lo ==================
__global__ __launch_bounds__(256) void pack_qkv_w(
    const float* __restrict__ q, const float* __restrict__ k,
    const float* __restrict__ v, __nv_bfloat16* __restrict__ h,
    __nv_bfloat16* __restrict__ l)
{
    int i4 = blockIdx.x * 256 + threadIdx.x;
    int row = i4 / (QKVN / 4);
    int c   = (i4 % (QKVN / 4)) * 4;
    const float* src = (c < 1024) ? q + (size_t)row * 1024 + c
                     : (c < 2048) ? k + (size_t)row * 1024 + (c - 1024)
                                  : v + (size_t)row * 1024 + (c - 2048);
    float4 vv = *(const float4*)src;
    __nv_bfloat162 h01, l01, h23, l23;
    split2(vv.x, vv.y, h01, l01);
    split2(vv.z, vv.w, h23, l23);
    ((__nv_bfloat162*)h)[i4 * 2]     = h01;
    ((__nv_bfloat162*)h)[i4 * 2 + 1] = h23;
    ((__nv_bfloat162*)l)[i4 * 2]     = l01;
    ((__nv_bfloat162*)l)[i4 * 2 + 1] = l23;
}
__global__ __launch_bounds__(256) void pack_qkv_b(
    const float* __restrict__ q, const float* __restrict__ k,
    const float* __restrict__ v, float* __restrict__ o)
{
    int idx = blockIdx.x * 256 + threadIdx.x;
    o[idx] = (idx < 1024) ? q[idx] : (idx < 2048) ? k[idx - 1024] : v[idx - 2048];
}

// ================== GEMM: C = A*B + bias, bf16x3 via mma.sync ==================
// 128x128 tile, 256 threads, 2(m)x4(n) warps, BK=32, double-buffered cp.async.
// occ 2 (151KB smem / <=128 regs). Register plan: 64 acc + 32 resident B frags
// + 8 streamed A frags + addressing ~= 119 -> no spills.
#define GM_STAGE 37888
template<int ACT, int WF32, int WSPLIT>
__global__ __launch_bounds__(256, 2) void gemm_bf16x3(
    const __nv_bfloat16* __restrict__ Ah, const __nv_bfloat16* __restrict__ Al,
    const __nv_bfloat16* __restrict__ Bh, const __nv_bfloat16* __restrict__ Bl,
    const float* __restrict__ bias,
    float* __restrict__ Cf, __nv_bfloat16* __restrict__ Ch,
    __nv_bfloat16* __restrict__ Cl, int M, int N, int K)
{
    extern __shared__ char sm[];
    const uint32_t smb = smem_u32(sm);
    const int tid = threadIdx.x, lane = tid & 31, wid = tid >> 5;
    const int warp_m = wid >> 2, warp_n = wid & 3;
    const int bm = blockIdx.y * 128, bn = blockIdx.x * 128;

    float c[4][4][4];
    #pragma unroll
    for (int i = 0; i < 4; i++)
        #pragma unroll
        for (int j = 0; j < 4; j++)
            #pragma unroll
            for (int q = 0; q < 4; q++) c[i][j][q] = 0.f;

    const int rowA  = (lane & 7) + ((lane >> 3) & 1) * 8;
    const int kselA = (lane >> 4) * 8;
    const int kB    = (lane & 7) + ((lane >> 3) & 1) * 8;
    const int nB    = ((lane >> 4) & 1) * 8;

    auto load_stage = [&](int s, int k0) {
        uint32_t base = smb + s * GM_STAGE;
        #pragma unroll
        for (int i = 0; i < 2; i++) {
            int cidx = tid + i * 256;
            int row = cidx >> 2, kc = (cidx & 3) << 3;
            size_t g = (size_t)(bm + row) * K + k0 + kc;
            CP16(base + row * 80 + kc * 2, Ah + g);
            CP16(base + 10240 + row * 80 + kc * 2, Al + g);
        }
        #pragma unroll
        for (int i = 0; i < 2; i++) {
            int cidx = tid + i * 256;
            int k = cidx >> 4, nc = (cidx & 15) << 3;
            size_t g = (size_t)(k0 + k) * N + bn + nc;
            CP16(base + 20480 + k * 272 + nc * 2, Bh + g);
            CP16(base + 29184 + k * 272 + nc * 2, Bl + g);
        }
        CPCOMMIT();
    };

    auto compute = [&](int s) {
        uint32_t bAh = smb + s * GM_STAGE;
        uint32_t bAl = bAh + 10240;
        uint32_t bBh = bAh + 20480;
        uint32_t bBl = bAh + 29184;
        #pragma unroll
        for (int ks = 0; ks < 2; ks++) {
            // resident B fragments for this ks: 8 n8-columns (hi+lo) = 32 regs
            uint32_t bh[4][2], bl[4][2];
            #pragma unroll
            for (int ntp = 0; ntp < 2; ntp++) {
                uint32_t off = (uint32_t)((ks * 16 + kB) * 272 +
                                          (warp_n * 32 + ntp * 16 + nB) * 2);
                uint32_t rh[4], rl[4];
                ldsm4t(rh, bBh + off);
                ldsm4t(rl, bBl + off);
                bh[2*ntp][0] = rh[0]; bh[2*ntp][1] = rh[1];
                bh[2*ntp+1][0] = rh[2]; bh[2*ntp+1][1] = rh[3];
                bl[2*ntp][0] = rl[0]; bl[2*ntp][1] = rl[1];
                bl[2*ntp+1][0] = rl[2]; bl[2*ntp+1][1] = rl[3];
            }
            // stream A fragments: 8 transient regs per mt, consumed immediately
            #pragma unroll
            for (int mt = 0; mt < 4; mt++) {
                uint32_t off = (uint32_t)((warp_m * 64 + mt * 16 + rowA) * 80 +
                                          (ks * 16 + kselA) * 2);
                uint32_t ah[4], al[4];
                ldsm4(ah, bAh + off);
                ldsm4(al, bAl + off);
                #pragma unroll
                for (int nt = 0; nt < 4; nt++) {
                    mma_bf16(c[mt][nt], ah, bh[nt]);
                    mma_bf16(c[mt][nt], ah, bl[nt]);
                    mma_bf16(c[mt][nt], al, bh[nt]);
                }
            }
        }
    };

    const int nt_k = K >> 5;
    load_stage(0, 0);
    for (int t = 0; t < nt_k; t++) {
        if (t + 1 < nt_k) { load_stage((t + 1) & 1, (t + 1) << 5); CPWAIT1(); }
        else              { CPWAIT0(); }
        __syncthreads();
        compute(t & 1);
        __syncthreads();
    }

    const int g = lane >> 2, tig = lane & 3;
    #pragma unroll
    for (int mt = 0; mt < 4; mt++) {
        #pragma unroll
        for (int nt = 0; nt < 4; nt++) {
            int col = bn + warp_n * 32 + nt * 8 + tig * 2;
            float b0 = bias[col], b1 = bias[col + 1];
            #pragma unroll
            for (int half = 0; half < 2; half++) {
                int row = bm + warp_m * 64 + mt * 16 + g + half * 8;
                float v0 = c[mt][nt][half * 2 + 0] + b0;
                float v1 = c[mt][nt][half * 2 + 1] + b1;
                if (ACT) { v0 = gelu_exact(v0); v1 = gelu_exact(v1); }
                if (WF32)
                    *(float2*)&Cf[(size_t)row * N + col] = make_float2(v0, v1);
                if (WSPLIT) {
                    __nv_bfloat162 h2, l2;
                    split2(v0, v1, h2, l2);
                    *(__nv_bfloat162*)&Ch[(size_t)row * N + col] = h2;
                    *(__nv_bfloat162*)&Cl[(size_t)row * N + col] = l2;
                }
            }
        }
    }
}

// ================== fused flash attention ==================
#define FA_QH   0
#define FA_QL   18432
#define FA_K(s) (36864 + (s) * 73728)
#define FA_MASK 184320
#define FA_SMEM 188416

__global__ __launch_bounds__(256) void flash_attn(
    const __nv_bfloat16* __restrict__ qkvh, const __nv_bfloat16* __restrict__ qkvl,
    const float* __restrict__ mask, const float* __restrict__ head_mask,
    int layer, __nv_bfloat16* __restrict__ Ch, __nv_bfloat16* __restrict__ Cl)
{
    extern __shared__ char sm[];
    const uint32_t smb = smem_u32(sm);
    const float* sm_mask = (const float*)(sm + FA_MASK);
    const int tid = threadIdx.x, lane = tid & 31, wid = tid >> 5;
    const int bh = blockIdx.y, b = bh >> 4, h = bh & 15;
    const int si = blockIdx.x * 128;
    const float hm = head_mask[layer * HH + h];

    #pragma unroll
    for (int i = 0; i < 4; i++) {
        int idx = tid + i * 256;
        int r = idx >> 3, cc = (idx & 7) << 3;
        size_t gq = (size_t)(b * SS + si + r) * QKVN + h * 64 + cc;
        CP16(smb + FA_QH + r * 144 + cc * 2, qkvh + gq);
        CP16(smb + FA_QL + r * 144 + cc * 2, qkvl + gq);
    }
    CP16(smb + FA_MASK + tid * 16, mask + b * SS + tid * 4);

    auto load_kv = [&](int s, int t0) {
        uint32_t base = smb + FA_K(s);
        #pragma unroll
        for (int i = 0; i < 4; i++) {
            int idx = tid + i * 256;
            int r = idx >> 3, cc = (idx & 7) << 3;
            size_t gk = (size_t)(b * SS + t0 + r) * QKVN + 1024 + h * 64 + cc;
            size_t gv = (size_t)(b * SS + t0 + r) * QKVN + 2048 + h * 64 + cc;
            CP16(base + r * 144 + cc * 2, qkvh + gk);
            CP16(base + 18432 + r * 144 + cc * 2, qkvl + gk);
            CP16(base + 36864 + r * 144 + cc * 2, qkvh + gv);
            CP16(base + 55296 + r * 144 + cc * 2, qkvl + gv);
        }
        CPCOMMIT();
    };
    load_kv(0, 0);

    const int rowA  = (lane & 7) + ((lane >> 3) & 1) * 8;
    const int kselA = (lane >> 4) * 8;
    const int rowK  = (lane & 7) + ((lane >> 4) & 1) * 8;
    const int dselK = ((lane >> 3) & 1) * 8;
    const int kB    = (lane & 7) + ((lane >> 3) & 1) * 8;
    const int nB    = ((lane >> 4) & 1) * 8;
    const int g = lane >> 2, tig = lane & 3;

    float m_prev0 = -INFINITY, m_prev1 = -INFINITY;
    float l0 = 0.f, l1 = 0.f;
    float acc[8][4];
    #pragma unroll
    for (int i = 0; i < 8; i++)
        #pragma unroll
        for (int q = 0; q < 4; q++) acc[i][q] = 0.f;

    const float scale = 0.125f;

    for (int kc = 0; kc < SS / 128; kc++) {
        const int s = kc & 1;
        if (kc + 1 < SS / 128) { load_kv((kc + 1) & 1, (kc + 1) * 128); CPWAIT1(); }
        else                   { CPWAIT0(); }
        __syncthreads();

        float c[16][4];
        #pragma unroll
        for (int i = 0; i < 16; i++)
            #pragma unroll
            for (int q = 0; q < 4; q++) c[i][q] = 0.f;

        uint32_t kb_h = smb + FA_K(s), kb_l = kb_h + 18432;
        #pragma unroll
        for (int ks = 0; ks < 4; ks++) {
            uint32_t ah[4], al[4];
            uint32_t offa = (uint32_t)((wid * 16 + rowA) * 144 + (ks * 16 + kselA) * 2);
            ldsm4(ah, smb + FA_QH + offa);
            ldsm4(al, smb + FA_QL + offa);
            #pragma unroll
            for (int ntp = 0; ntp < 8; ntp++) {
                uint32_t offb = (uint32_t)((ntp * 16 + rowK) * 144 + (ks * 16 + dselK) * 2);
                uint32_t r4[4];
                ldsm4(r4, kb_h + offb);
                uint32_t bhe[2] = { r4[0], r4[1] }, bho[2] = { r4[2], r4[3] };
                ldsm4(r4, kb_l + offb);
                uint32_t ble[2] = { r4[0], r4[1] }, blo[2] = { r4[2], r4[3] };
                mma_bf16(c[2*ntp],   ah, bhe);
                mma_bf16(c[2*ntp],   ah, ble);
                mma_bf16(c[2*ntp],   al, bhe);
                mma_bf16(c[2*ntp+1], ah, bho);
                mma_bf16(c[2*ntp+1], ah, blo);
                mma_bf16(c[2*ntp+1], al, bho);
            }
        }

        float mx0 = -INFINITY, mx1 = -INFINITY;
        #pragma unroll
        for (int nt = 0; nt < 16; nt++) {
            int col = kc * 128 + nt * 8 + tig * 2;
            float mk0 = sm_mask[col], mk1 = sm_mask[col + 1];
            c[nt][0] = c[nt][0] * scale + mk0;
            c[nt][1] = c[nt][1] * scale + mk1;
            c[nt][2] = c[nt][2] * scale + mk0;
            c[nt][3] = c[nt][3] * scale + mk1;
            mx0 = fmaxf(mx0, fmaxf(c[nt][0], c[nt][1]));
            mx1 = fmaxf(mx1, fmaxf(c[nt][2], c[nt][3]));
        }
        mx0 = fmaxf(mx0, __shfl_xor_sync(0xffffffffu, mx0, 1));
        mx0 = fmaxf(mx0, __shfl_xor_sync(0xffffffffu, mx0, 2));
        mx1 = fmaxf(mx1, __shfl_xor_sync(0xffffffffu, mx1, 1));
        mx1 = fmaxf(mx1, __shfl_xor_sync(0xffffffffu, mx1, 2));

        float mn0 = fmaxf(m_prev0, mx0), mn1 = fmaxf(m_prev1, mx1);
        float al0 = __expf(m_prev0 - mn0), al1 = __expf(m_prev1 - mn1);
        m_prev0 = mn0; m_prev1 = mn1;

        float s0 = 0.f, s1 = 0.f;
        #pragma unroll
        for (int nt = 0; nt < 16; nt++) {
            c[nt][0] = __expf(c[nt][0] - mn0);
            c[nt][1] = __expf(c[nt][1] - mn0);
            c[nt][2] = __expf(c[nt][2] - mn1);
            c[nt][3] = __expf(c[nt][3] - mn1);
            s0 += c[nt][0] + c[nt][1];
            s1 += c[nt][2] + c[nt][3];
        }
        s0 += __shfl_xor_sync(0xffffffffu, s0, 1);
        s0 += __shfl_xor_sync(0xffffffffu, s0, 2);
        s1 += __shfl_xor_sync(0xffffffffu, s1, 1);
        s1 += __shfl_xor_sync(0xffffffffu, s1, 2);
        l0 = l0 * al0 + s0;
        l1 = l1 * al1 + s1;

        #pragma unroll
        for (int d = 0; d < 8; d++) {
            acc[d][0] *= al0; acc[d][1] *= al0;
            acc[d][2] *= al1; acc[d][3] *= al1;
        }

        uint32_t vb_h = smb + FA_K(s) + 36864, vb_l = vb_h + 18432;
        #pragma unroll
        for (int ks2 = 0; ks2 < 8; ks2++) {
            uint32_t pah[4], pal[4];
            __nv_bfloat162 h2, l2;
            split2(c[2*ks2][0],   c[2*ks2][1],   h2, l2); pah[0] = b2u(h2); pal[0] = b2u(l2);
            split2(c[2*ks2][2],   c[2*ks2][3],   h2, l2); pah[1] = b2u(h2); pal[1] = b2u(l2);
            split2(c[2*ks2+1][0], c[2*ks2+1][1], h2, l2); pah[2] = b2u(h2); pal[2] = b2u(l2);
            split2(c[2*ks2+1][2], c[2*ks2+1][3], h2, l2); pah[3] = b2u(h2); pal[3] = b2u(l2);
            #pragma unroll
            for (int ntp2 = 0; ntp2 < 4; ntp2++) {
                uint32_t offv = (uint32_t)((ks2 * 16 + kB) * 144 + (ntp2 * 16 + nB) * 2);
                uint32_t r4[4];
                ldsm4t(r4, vb_h + offv);
                uint32_t vhe[2] = { r4[0], r4[1] }, vho[2] = { r4[2], r4[3] };
                ldsm4t(r4, vb_l + offv);
                uint32_t vle[2] = { r4[0], r4[1] }, vlo[2] = { r4[2], r4[3] };
                mma_bf16(acc[2*ntp2],   pah, vhe);
                mma_bf16(acc[2*ntp2],   pal, vhe);
                mma_bf16(acc[2*ntp2],   pah, vle);
                mma_bf16(acc[2*ntp2+1], pah, vho);
                mma_bf16(acc[2*ntp2+1], pal, vho);
                mma_bf16(acc[2*ntp2+1], pah, vlo);
            }
        }
        __syncthreads();
    }

    const float inv0 = hm / l0, inv1 = hm / l1;
    const int row0 = si + wid * 16 + g, row1 = row0 + 8;
    #pragma unroll
    for (int d = 0; d < 8; d++) {
        int col = h * 64 + d * 8 + tig * 2;
        __nv_bfloat162 h2, l2;
        split2(acc[d][0] * inv0, acc[d][1] * inv0, h2, l2);
        size_t o0 = (size_t)(b * SS + row0) * DD + col;
        *(__nv_bfloat162*)&Ch[o0] = h2;
        *(__nv_bfloat162*)&Cl[o0] = l2;
        split2(acc[d][2] * inv1, acc[d][3] * inv1, h2, l2);
        size_t o1 = (size_t)(b * SS + row1) * DD + col;
        *(__nv_bfloat162*)&Ch[o1] = h2;
        *(__nv_bfloat162*)&Cl[o1] = l2;
    }
}

// ================== residual + LayerNorm (+ split outputs) ==================
__global__ __launch_bounds__(256) void ln_residual(
    const float* __restrict__ x, const float* __restrict__ y,
    const float* __restrict__ g, const float* __restrict__ b,
    float* __restrict__ out, __nv_bfloat16* __restrict__ oh,
    __nv_bfloat16* __restrict__ ol)
{
    const int row = blockIdx.x;
    const int tid = threadIdx.x;
    const float4* xp = (const float4*)(x + (size_t)row * DD);
    const float4* yp = (const float4*)(y + (size_t)row * DD);

    float4 xv = xp[tid];
    float4 yv = yp[tid];
    float4 s4 = make_float4(xv.x + yv.x, xv.y + yv.y, xv.z + yv.z, xv.w + yv.w);

    float s  = s4.x + s4.y + s4.z + s4.w;
    float ss = s4.x * s4.x + s4.y * s4.y + s4.z * s4.z + s4.w * s4.w;

    const int lane = tid & 31, warp = tid >> 5;
    #pragma unroll
    for (int off = 16; off > 0; off >>= 1) {
        s  += __shfl_xor_sync(0xffffffffu, s, off);
        ss += __shfl_xor_sync(0xffffffffu, ss, off);
    }
    __shared__ float ws[8], wss[8];
    if (lane == 0) { ws[warp] = s; wss[warp] = ss; }
    __syncthreads();
    if (warp == 0) {
        float a  = (lane < 8) ? ws[lane]  : 0.f;
        float aa = (lane < 8) ? wss[lane] : 0.f;
        #pragma unroll
        for (int off = 4; off > 0; off >>= 1) {
            a  += __shfl_xor_sync(0xffffffffu, a, off);
            aa += __shfl_xor_sync(0xffffffffu, aa, off);
        }
        if (lane == 0) { ws[0] = a; wss[0] = aa; }
    }
    __syncthreads();
    const float mean = ws[0] * (1.0f / DD);
    const float var  = wss[0] * (1.0f / DD) - mean * mean;
    const float inv  = rsqrtf(var + 1e-12f);

    const float4 gv = ((const float4*)g)[tid];
    const float4 bv = ((const float4*)b)[tid];
    float4 o;
    o.x = (s4.x - mean) * inv * gv.x + bv.x;
    o.y = (s4.y - mean) * inv * gv.y + bv.y;
    o.z = (s4.z - mean) * inv * gv.z + bv.z;
    o.w = (s4.w - mean) * inv * gv.w + bv.w;
    ((float4*)(out + (size_t)row * DD))[tid] = o;

    __nv_bfloat162 h01, l01, h23, l23;
    split2(o.x, o.y, h01, l01);
    split2(o.z, o.w, h23, l23);
    __nv_bfloat162* hp = (__nv_bfloat162*)(oh + (size_t)row * DD);
    __nv_bfloat162* lp = (__nv_bfloat162*)(ol + (size_t)row * DD);
    hp[tid * 2] = h01; hp[tid * 2 + 1] = h23;
    lp[tid * 2] = l01; lp[tid * 2 + 1] = l23;
}

// ================== host orchestration ==================
extern "C" void kernel_launch(void* const* d_in, const int* in_sizes, int n_in,
                              void* d_out, int out_size)
{
    const float* hidden = (const float*)d_in[0];
    const float* amask  = (const float*)d_in[1];
    const float* hmask  = (const float*)d_in[2];
    const float* q_w    = (const float*)d_in[3];
    const float* q_b    = (const float*)d_in[4];
    const float* k_w    = (const float*)d_in[5];
    const float* k_b    = (const float*)d_in[6];
    const float* v_w    = (const float*)d_in[7];
    const float* v_b    = (const float*)d_in[8];
    const float* o_w    = (const float*)d_in[9];
    const float* o_b    = (const float*)d_in[10];
    const float* aln_g  = (const float*)d_in[11];
    const float* aln_b  = (const float*)d_in[12];
    const float* w1     = (const float*)d_in[13];
    const float* b1     = (const float*)d_in[14];
    const float* w2     = (const float*)d_in[15];
    const float* b2     = (const float*)d_in[16];
    const float* fln_g  = (const float*)d_in[17];
    const float* fln_b  = (const float*)d_in[18];
    float* out = (float*)d_out;

    float *tmpb, *attnb, *hsb, *bqkvb;
    __nv_bfloat16 *hs_h, *hs_l, *qkv_h, *qkv_l;
    __nv_bfloat16 *ctx_h, *ctx_l, *attn_h, *attn_l, *ffn1_h, *ffn1_l;
    __nv_bfloat16 *wqkv_h, *wqkv_l, *wo_h, *wo_l, *w1_h, *w1_l, *w2_h, *w2_l;
    cudaGetSymbolAddress((void**)&tmpb,  g_tmp);
    cudaGetSymbolAddress((void**)&attnb, g_attn);
    cudaGetSymbolAddress((void**)&hsb,   g_hs);
    cudaGetSymbolAddress((void**)&bqkvb, g_bqkv);
    cudaGetSymbolAddress((void**)&hs_h, g_hs_h);   cudaGetSymbolAddress((void**)&hs_l, g_hs_l);
    cudaGetSymbolAddress((void**)&qkv_h, g_qkv_h); cudaGetSymbolAddress((void**)&qkv_l, g_qkv_l);
    cudaGetSymbolAddress((void**)&ctx_h, g_ctx_h); cudaGetSymbolAddress((void**)&ctx_l, g_ctx_l);
    cudaGetSymbolAddress((void**)&attn_h, g_attn_h); cudaGetSymbolAddress((void**)&attn_l, g_attn_l);
    cudaGetSymbolAddress((void**)&ffn1_h, g_ffn1_h); cudaGetSymbolAddress((void**)&ffn1_l, g_ffn1_l);
    cudaGetSymbolAddress((void**)&wqkv_h, g_wqkv_h); cudaGetSymbolAddress((void**)&wqkv_l, g_wqkv_l);
    cudaGetSymbolAddress((void**)&wo_h, g_wo_h);   cudaGetSymbolAddress((void**)&wo_l, g_wo_l);
    cudaGetSymbolAddress((void**)&w1_h, g_w1_h);   cudaGetSymbolAddress((void**)&w1_l, g_w1_l);
    cudaGetSymbolAddress((void**)&w2_h, g_w2_h);   cudaGetSymbolAddress((void**)&w2_l, g_w2_l);

    cudaFuncSetAttribute(gemm_bf16x3<0,0,1>, cudaFuncAttributeMaxDynamicSharedMemorySize, 2*GM_STAGE);
    cudaFuncSetAttribute(gemm_bf16x3<0,1,0>, cudaFuncAttributeMaxDynamicSharedMemorySize, 2*GM_STAGE);
    cudaFuncSetAttribute(gemm_bf16x3<1,0,1>, cudaFuncAttributeMaxDynamicSharedMemorySize, 2*GM_STAGE);
    cudaFuncSetAttribute(flash_attn, cudaFuncAttributeMaxDynamicSharedMemorySize, FA_SMEM);

    pack_qkv_w<<<(DD*QKVN/4)/256, 256>>>(q_w, k_w, v_w, wqkv_h, wqkv_l);
    pack_qkv_b<<<QKVN/256, 256>>>(q_b, k_b, v_b, bqkvb);
    split_bf16<<<(DD*DD)/1024, 256>>>(o_w, wo_h, wo_l);
    split_bf16<<<(LL*DD*DFF)/1024, 256>>>(w1, w1_h, w1_l);
    split_bf16<<<(LL*DFF*DD)/1024, 256>>>(w2, w2_h, w2_l);
    split_bf16<<<(MM*DD)/1024, 256>>>(hidden, hs_h, hs_l);

    const dim3 g1(DD/128, MM/128);
    const dim3 g4(DFF/128, MM/128);
    const dim3 gqkv(QKVN/128, MM/128);
    const dim3 fa_grid(SS/128, BB*HH);

    for (int l = 0; l < LL; l++) {
        const float* hsin_f = (l == 0) ? hidden : hsb;
        float* hsout = (l == LL - 1) ? out : hsb;

        gemm_bf16x3<0,0,1><<<gqkv, 256, 2*GM_STAGE>>>(hs_h, hs_l, wqkv_h, wqkv_l,
            bqkvb, nullptr, qkv_h, qkv_l, MM, QKVN, DD);

        flash_attn<<<fa_grid, 256, FA_SMEM>>>(qkv_h, qkv_l, amask, hmask, l,
                                              ctx_h, ctx_l);

        gemm_bf16x3<0,1,0><<<g1, 256, 2*GM_STAGE>>>(ctx_h, ctx_l, wo_h, wo_l, o_b,
            tmpb, nullptr, nullptr, MM, DD, DD);
        ln_residual<<<MM, 256>>>(hsin_f, tmpb, aln_g, aln_b, attnb, attn_h, attn_l);

        gemm_bf16x3<1,0,1><<<g4, 256, 2*GM_STAGE>>>(attn_h, attn_l,
            w1_h + (size_t)l*DD*DFF, w1_l + (size_t)l*DD*DFF, b1 + (size_t)l*DFF,
            nullptr, ffn1_h, ffn1_l, MM, DFF, DD);
        gemm_bf16x3<0,1,0><<<g1, 256, 2*GM_STAGE>>>(ffn1_h, ffn1_l,
            w2_h + (size_t)l*DFF*DD, w2_l + (size_t)l*DFF*DD, b2 + (size_t)l*DD,
            tmpb, nullptr, nullptr, MM, DD, DFF);
        ln_residual<<<MM, 256>>>(attnb, tmpb, fln_g + (size_t)l*DD,
                                 fln_b + (size_t)l*DD, hsout, hs_h, hs_l);
    }
}

// round 8
// speedup vs baseline: 1.4885x; 1.3287x over previous
#include <cuda_runtime.h>
#include <cuda_fp16.h>
#include <math.h>
#include <stdint.h>

// ---------------- problem constants ----------------
#define BB   4
#define SS   1024
#define DD   1024
#define HH   16
#define HDIM 64
#define LL   2
#define DFF  4096
#define MM   (BB*SS)
#define QKVN 3072

// ---------------- static device scratch ----------------
__device__ __align__(256) float g_tmp [(size_t)MM*DD];
__device__ __align__(256) float g_attn[(size_t)MM*DD];
__device__ __align__(256) float g_hs  [(size_t)MM*DD];

__device__ __align__(256) __half g_hs_h [(size_t)MM*DD];
__device__ __align__(256) __half g_hs_l [(size_t)MM*DD];
__device__ __align__(256) __half g_qkv_h[(size_t)MM*QKVN];
__device__ __align__(256) __half g_qkv_l[(size_t)MM*QKVN];
__device__ __align__(256) __half g_ctx_h[(size_t)MM*DD];
__device__ __align__(256) __half g_ctx_l[(size_t)MM*DD];
__device__ __align__(256) __half g_attn_h[(size_t)MM*DD];
__device__ __align__(256) __half g_attn_l[(size_t)MM*DD];
__device__ __align__(256) __half g_ffn1_h[(size_t)MM*DFF];
__device__ __align__(256) __half g_ffn1_l[(size_t)MM*DFF];

__device__ __align__(256) __half g_wqkv[(size_t)DD*QKVN];
__device__ __align__(256) float  g_bqkv[QKVN];
__device__ __align__(256) __half g_wo  [(size_t)DD*DD];
__device__ __align__(256) __half g_w1  [(size_t)LL*DD*DFF];
__device__ __align__(256) __half g_w2  [(size_t)LL*DFF*DD];

// ---------------- asm helpers ----------------
__device__ __forceinline__ uint32_t smem_u32(const void* p) {
    uint32_t a;
    asm("{ .reg .u64 t; cvta.to.shared.u64 t, %1; cvt.u32.u64 %0, t; }"
        : "=r"(a) : "l"(p));
    return a;
}
#define CP16(dst, src) asm volatile("cp.async.cg.shared.global [%0], [%1], 16;" :: "r"(dst), "l"(src) : "memory")
#define CPCOMMIT()     asm volatile("cp.async.commit_group;" ::: "memory")
#define CPWAIT1()      asm volatile("cp.async.wait_group 1;" ::: "memory")
#define CPWAIT0()      asm volatile("cp.async.wait_group 0;" ::: "memory")

__device__ __forceinline__ void ldsm4(uint32_t* r, uint32_t a) {
    asm volatile("ldmatrix.sync.aligned.m8n8.x4.shared.b16 {%0,%1,%2,%3}, [%4];"
        : "=r"(r[0]), "=r"(r[1]), "=r"(r[2]), "=r"(r[3]) : "r"(a));
}
__device__ __forceinline__ void ldsm4t(uint32_t* r, uint32_t a) {
    asm volatile("ldmatrix.sync.aligned.m8n8.x4.trans.shared.b16 {%0,%1,%2,%3}, [%4];"
        : "=r"(r[0]), "=r"(r[1]), "=r"(r[2]), "=r"(r[3]) : "r"(a));
}
__device__ __forceinline__ void mma_f16(float* c, const uint32_t* a, const uint32_t* b) {
    asm volatile(
        "mma.sync.aligned.m16n8k16.row.col.f32.f16.f16.f32 "
        "{%0,%1,%2,%3}, {%4,%5,%6,%7}, {%8,%9}, {%0,%1,%2,%3};"
        : "+f"(c[0]), "+f"(c[1]), "+f"(c[2]), "+f"(c[3])
        : "r"(a[0]), "r"(a[1]), "r"(a[2]), "r"(a[3]), "r"(b[0]), "r"(b[1]));
}
__device__ __forceinline__ float gelu_exact(float x) {
    return 0.5f * x * (1.0f + erff(x * 0.70710678118654752440f));
}
// fp32 -> fp16 hi/lo pair (packed half2 as u32)
__device__ __forceinline__ void split2h(float v0, float v1,
                                        uint32_t& h, uint32_t& l) {
    __half h0 = __float2half_rn(v0);
    __half h1 = __float2half_rn(v1);
    __half l0 = __float2half_rn(v0 - __half2float(h0));
    __half l1 = __float2half_rn(v1 - __half2float(h1));
    __half2 hh = __halves2half2(h0, h1);
    __half2 ll = __halves2half2(l0, l1);
    h = *reinterpret_cast<uint32_t*>(&hh);
    l = *reinterpret_cast<uint32_t*>(&ll);
}
__device__ __forceinline__ uint32_t pack2h(float v0, float v1) {
    __half2 p = __floats2half2_rn(v0, v1);
    return *reinterpret_cast<uint32_t*>(&p);
}

// ================== split convert: fp32 -> fp16 hi/lo ==================
__global__ __launch_bounds__(256) void split_fp16(
    const float* __restrict__ src, __half* __restrict__ h,
    __half* __restrict__ l)
{
    int idx = blockIdx.x * 256 + threadIdx.x;
    float4 v = ((const float4*)src)[idx];
    uint32_t h01, l01, h23, l23;
    split2h(v.x, v.y, h01, l01);
    split2h(v.z, v.w, h23, l23);
    ((uint32_t*)h)[idx * 2]     = h01;
    ((uint32_t*)h)[idx * 2 + 1] = h23;
    ((uint32_t*)l)[idx * 2]     = l01;
    ((uint32_t*)l)[idx * 2 + 1] = l23;
}

// ================== single convert: fp32 -> fp16 ==================
__global__ __launch_bounds__(256) void cvt_fp16(
    const float* __restrict__ src, __half* __restrict__ dst)
{
    int idx = blockIdx.x * 256 + threadIdx.x;
    float4 v = ((const float4*)src)[idx];
    ((uint32_t*)dst)[idx * 2]     = pack2h(v.x, v.y);
    ((uint32_t*)dst)[idx * 2 + 1] = pack2h(v.z, v.w);
}

// ================== pack QKV weights: [D,3D] single fp16 ==================
__global__ __launch_bounds__(256) void pack_qkv_w(
    const float* __restrict__ q, const float* __restrict__ k,
    const float* __restrict__ v, __half* __restrict__ dst)
{
    int i4 = blockIdx.x * 256 + threadIdx.x;
    int row = i4 / (QKVN / 4);
    int c   = (i4 % (QKVN / 4)) * 4;
    const float* src = (c < 1024) ? q + (size_t)row * 1024 + c
                     : (c < 2048) ? k + (size_t)row * 1024 + (c - 1024)
                                  : v + (size_t)row * 1024 + (c - 2048);
    float4 vv = *(const float4*)src;
    ((uint32_t*)dst)[i4 * 2]     = pack2h(vv.x, vv.y);
    ((uint32_t*)dst)[i4 * 2 + 1] = pack2h(vv.z, vv.w);
}
__global__ __launch_bounds__(256) void pack_qkv_b(
    const float* __restrict__ q, const float* __restrict__ k,
    const float* __restrict__ v, float* __restrict__ o)
{
    int idx = blockIdx.x * 256 + threadIdx.x;
    o[idx] = (idx < 1024) ? q[idx] : (idx < 2048) ? k[idx - 1024] : v[idx - 2048];
}

// ================== GEMM: C = A*B + bias, fp16x2 via mma.sync ==================
// A = a_h + a_l (fp16 pair), B single fp16. 2 MMAs per logical MMA.
// 128x128 tile, 256 threads, 2(m)x4(n) warps, BK=32, double-buffered, occ 2.
// stage: A_h[128][80B] A_l[128][80B] B[32][272B] = 29184 B
#define GM_STAGE 29184
template<int ACT, int WF32, int WSPLIT>
__global__ __launch_bounds__(256, 2) void gemm_fp16x2(
    const __half* __restrict__ Ah, const __half* __restrict__ Al,
    const __half* __restrict__ Bw, const float* __restrict__ bias,
    float* __restrict__ Cf, __half* __restrict__ Ch,
    __half* __restrict__ Cl, int M, int N, int K)
{
    extern __shared__ char sm[];
    const uint32_t smb = smem_u32(sm);
    const int tid = threadIdx.x, lane = tid & 31, wid = tid >> 5;
    const int warp_m = wid >> 2, warp_n = wid & 3;
    const int bm = blockIdx.y * 128, bn = blockIdx.x * 128;

    float c[4][4][4];
    #pragma unroll
    for (int i = 0; i < 4; i++)
        #pragma unroll
        for (int j = 0; j < 4; j++)
            #pragma unroll
            for (int q = 0; q < 4; q++) c[i][j][q] = 0.f;

    const int rowA  = (lane & 7) + ((lane >> 3) & 1) * 8;
    const int kselA = (lane >> 4) * 8;
    const int kB    = (lane & 7) + ((lane >> 3) & 1) * 8;
    const int nB    = ((lane >> 4) & 1) * 8;

    auto load_stage = [&](int s, int k0) {
        uint32_t base = smb + s * GM_STAGE;
        #pragma unroll
        for (int i = 0; i < 2; i++) {
            int cidx = tid + i * 256;
            int row = cidx >> 2, kc = (cidx & 3) << 3;
            size_t g = (size_t)(bm + row) * K + k0 + kc;
            CP16(base + row * 80 + kc * 2, Ah + g);
            CP16(base + 10240 + row * 80 + kc * 2, Al + g);
        }
        #pragma unroll
        for (int i = 0; i < 2; i++) {
            int cidx = tid + i * 256;
            int k = cidx >> 4, nc = (cidx & 15) << 3;
            size_t g = (size_t)(k0 + k) * N + bn + nc;
            CP16(base + 20480 + k * 272 + nc * 2, Bw + g);
        }
        CPCOMMIT();
    };

    auto compute = [&](int s) {
        uint32_t bAh = smb + s * GM_STAGE;
        uint32_t bAl = bAh + 10240;
        uint32_t bB  = bAh + 20480;
        #pragma unroll
        for (int ks = 0; ks < 2; ks++) {
            uint32_t bf[4][2];
            #pragma unroll
            for (int ntp = 0; ntp < 2; ntp++) {
                uint32_t off = (uint32_t)((ks * 16 + kB) * 272 +
                                          (warp_n * 32 + ntp * 16 + nB) * 2);
                uint32_t r[4];
                ldsm4t(r, bB + off);
                bf[2*ntp][0] = r[0]; bf[2*ntp][1] = r[1];
                bf[2*ntp+1][0] = r[2]; bf[2*ntp+1][1] = r[3];
            }
            #pragma unroll
            for (int mt = 0; mt < 4; mt++) {
                uint32_t off = (uint32_t)((warp_m * 64 + mt * 16 + rowA) * 80 +
                                          (ks * 16 + kselA) * 2);
                uint32_t ah[4], al[4];
                ldsm4(ah, bAh + off);
                ldsm4(al, bAl + off);
                #pragma unroll
                for (int nt = 0; nt < 4; nt++) {
                    mma_f16(c[mt][nt], ah, bf[nt]);
                    mma_f16(c[mt][nt], al, bf[nt]);
                }
            }
        }
    };

    const int nt_k = K >> 5;
    load_stage(0, 0);
    for (int t = 0; t < nt_k; t++) {
        if (t + 1 < nt_k) { load_stage((t + 1) & 1, (t + 1) << 5); CPWAIT1(); }
        else              { CPWAIT0(); }
        __syncthreads();
        compute(t & 1);
        __syncthreads();
    }

    const int g = lane >> 2, tig = lane & 3;
    #pragma unroll
    for (int mt = 0; mt < 4; mt++) {
        #pragma unroll
        for (int nt = 0; nt < 4; nt++) {
            int col = bn + warp_n * 32 + nt * 8 + tig * 2;
            float b0 = bias[col], b1 = bias[col + 1];
            #pragma unroll
            for (int half = 0; half < 2; half++) {
                int row = bm + warp_m * 64 + mt * 16 + g + half * 8;
                float v0 = c[mt][nt][half * 2 + 0] + b0;
                float v1 = c[mt][nt][half * 2 + 1] + b1;
                if (ACT) { v0 = gelu_exact(v0); v1 = gelu_exact(v1); }
                if (WF32)
                    *(float2*)&Cf[(size_t)row * N + col] = make_float2(v0, v1);
                if (WSPLIT) {
                    uint32_t h2, l2;
                    split2h(v0, v1, h2, l2);
                    *(uint32_t*)&Ch[(size_t)row * N + col] = h2;
                    *(uint32_t*)&Cl[(size_t)row * N + col] = l2;
                }
            }
        }
    }
}

// ================== fused flash attention (fp16x2) ==================
// Q = q_h + q_l (2-term), K single, V = v_h + v_l, P single.
// smem: Qh 18432 | Ql 18432 | 2 stages of [K | Vh | Vl] 55296 | mask 4096
#define FA_QH   0
#define FA_QL   18432
#define FA_K(s) (36864 + (s) * 55296)
#define FA_MASK 147456
#define FA_SMEM 151552

__global__ __launch_bounds__(256) void flash_attn(
    const __half* __restrict__ qkvh, const __half* __restrict__ qkvl,
    const float* __restrict__ mask, const float* __restrict__ head_mask,
    int layer, __half* __restrict__ Ch, __half* __restrict__ Cl)
{
    extern __shared__ char sm[];
    const uint32_t smb = smem_u32(sm);
    const float* sm_mask = (const float*)(sm + FA_MASK);
    const int tid = threadIdx.x, lane = tid & 31, wid = tid >> 5;
    const int bh = blockIdx.y, b = bh >> 4, h = bh & 15;
    const int si = blockIdx.x * 128;
    const float hm = head_mask[layer * HH + h];

    #pragma unroll
    for (int i = 0; i < 4; i++) {
        int idx = tid + i * 256;
        int r = idx >> 3, cc = (idx & 7) << 3;
        size_t gq = (size_t)(b * SS + si + r) * QKVN + h * 64 + cc;
        CP16(smb + FA_QH + r * 144 + cc * 2, qkvh + gq);
        CP16(smb + FA_QL + r * 144 + cc * 2, qkvl + gq);
    }
    CP16(smb + FA_MASK + tid * 16, mask + b * SS + tid * 4);

    auto load_kv = [&](int s, int t0) {
        uint32_t base = smb + FA_K(s);
        #pragma unroll
        for (int i = 0; i < 4; i++) {
            int idx = tid + i * 256;
            int r = idx >> 3, cc = (idx & 7) << 3;
            size_t gk = (size_t)(b * SS + t0 + r) * QKVN + 1024 + h * 64 + cc;
            size_t gv = (size_t)(b * SS + t0 + r) * QKVN + 2048 + h * 64 + cc;
            CP16(base + r * 144 + cc * 2, qkvh + gk);
            CP16(base + 18432 + r * 144 + cc * 2, qkvh + gv);
            CP16(base + 36864 + r * 144 + cc * 2, qkvl + gv);
        }
        CPCOMMIT();
    };
    load_kv(0, 0);

    const int rowA  = (lane & 7) + ((lane >> 3) & 1) * 8;
    const int kselA = (lane >> 4) * 8;
    const int rowK  = (lane & 7) + ((lane >> 4) & 1) * 8;
    const int dselK = ((lane >> 3) & 1) * 8;
    const int kB    = (lane & 7) + ((lane >> 3) & 1) * 8;
    const int nB    = ((lane >> 4) & 1) * 8;
    const int g = lane >> 2, tig = lane & 3;

    float m_prev0 = -INFINITY, m_prev1 = -INFINITY;
    float l0 = 0.f, l1 = 0.f;
    float acc[8][4];
    #pragma unroll
    for (int i = 0; i < 8; i++)
        #pragma unroll
        for (int q = 0; q < 4; q++) acc[i][q] = 0.f;

    const float scale = 0.125f;

    for (int kc = 0; kc < SS / 128; kc++) {
        const int s = kc & 1;
        if (kc + 1 < SS / 128) { load_kv((kc + 1) & 1, (kc + 1) * 128); CPWAIT1(); }
        else                   { CPWAIT0(); }
        __syncthreads();

        float c[16][4];
        #pragma unroll
        for (int i = 0; i < 16; i++)
            #pragma unroll
            for (int q = 0; q < 4; q++) c[i][q] = 0.f;

        uint32_t kb = smb + FA_K(s);
        #pragma unroll
        for (int ks = 0; ks < 4; ks++) {
            uint32_t ah[4], al[4];
            uint32_t offa = (uint32_t)((wid * 16 + rowA) * 144 + (ks * 16 + kselA) * 2);
            ldsm4(ah, smb + FA_QH + offa);
            ldsm4(al, smb + FA_QL + offa);
            #pragma unroll
            for (int ntp = 0; ntp < 8; ntp++) {
                uint32_t offb = (uint32_t)((ntp * 16 + rowK) * 144 + (ks * 16 + dselK) * 2);
                uint32_t r4[4];
                ldsm4(r4, kb + offb);
                uint32_t be[2] = { r4[0], r4[1] }, bo[2] = { r4[2], r4[3] };
                mma_f16(c[2*ntp],   ah, be);
                mma_f16(c[2*ntp],   al, be);
                mma_f16(c[2*ntp+1], ah, bo);
                mma_f16(c[2*ntp+1], al, bo);
            }
        }

        float mx0 = -INFINITY, mx1 = -INFINITY;
        #pragma unroll
        for (int nt = 0; nt < 16; nt++) {
            int col = kc * 128 + nt * 8 + tig * 2;
            float mk0 = sm_mask[col], mk1 = sm_mask[col + 1];
            c[nt][0] = c[nt][0] * scale + mk0;
            c[nt][1] = c[nt][1] * scale + mk1;
            c[nt][2] = c[nt][2] * scale + mk0;
            c[nt][3] = c[nt][3] * scale + mk1;
            mx0 = fmaxf(mx0, fmaxf(c[nt][0], c[nt][1]));
            mx1 = fmaxf(mx1, fmaxf(c[nt][2], c[nt][3]));
        }
        mx0 = fmaxf(mx0, __shfl_xor_sync(0xffffffffu, mx0, 1));
        mx0 = fmaxf(mx0, __shfl_xor_sync(0xffffffffu, mx0, 2));
        mx1 = fmaxf(mx1, __shfl_xor_sync(0xffffffffu, mx1, 1));
        mx1 = fmaxf(mx1, __shfl_xor_sync(0xffffffffu, mx1, 2));

        float mn0 = fmaxf(m_prev0, mx0), mn1 = fmaxf(m_prev1, mx1);
        float al0 = __expf(m_prev0 - mn0), al1 = __expf(m_prev1 - mn1);
        m_prev0 = mn0; m_prev1 = mn1;

        float s0 = 0.f, s1 = 0.f;
        #pragma unroll
        for (int nt = 0; nt < 16; nt++) {
            c[nt][0] = __expf(c[nt][0] - mn0);
            c[nt][1] = __expf(c[nt][1] - mn0);
            c[nt][2] = __expf(c[nt][2] - mn1);
            c[nt][3] = __expf(c[nt][3] - mn1);
            s0 += c[nt][0] + c[nt][1];
            s1 += c[nt][2] + c[nt][3];
        }
        s0 += __shfl_xor_sync(0xffffffffu, s0, 1);
        s0 += __shfl_xor_sync(0xffffffffu, s0, 2);
        s1 += __shfl_xor_sync(0xffffffffu, s1, 1);
        s1 += __shfl_xor_sync(0xffffffffu, s1, 2);
        l0 = l0 * al0 + s0;
        l1 = l1 * al1 + s1;

        #pragma unroll
        for (int d = 0; d < 8; d++) {
            acc[d][0] *= al0; acc[d][1] *= al0;
            acc[d][2] *= al1; acc[d][3] *= al1;
        }

        uint32_t vb_h = smb + FA_K(s) + 18432, vb_l = smb + FA_K(s) + 36864;
        #pragma unroll
        for (int ks2 = 0; ks2 < 8; ks2++) {
            uint32_t pa[4];
            pa[0] = pack2h(c[2*ks2][0],   c[2*ks2][1]);
            pa[1] = pack2h(c[2*ks2][2],   c[2*ks2][3]);
            pa[2] = pack2h(c[2*ks2+1][0], c[2*ks2+1][1]);
            pa[3] = pack2h(c[2*ks2+1][2], c[2*ks2+1][3]);
            #pragma unroll
            for (int ntp2 = 0; ntp2 < 4; ntp2++) {
                uint32_t offv = (uint32_t)((ks2 * 16 + kB) * 144 + (ntp2 * 16 + nB) * 2);
                uint32_t r4[4];
                ldsm4t(r4, vb_h + offv);
                uint32_t vhe[2] = { r4[0], r4[1] }, vho[2] = { r4[2], r4[3] };
                ldsm4t(r4, vb_l + offv);
                uint32_t vle[2] = { r4[0], r4[1] }, vlo[2] = { r4[2], r4[3] };
                mma_f16(acc[2*ntp2],   pa, vhe);
                mma_f16(acc[2*ntp2],   pa, vle);
                mma_f16(acc[2*ntp2+1], pa, vho);
                mma_f16(acc[2*ntp2+1], pa, vlo);
            }
        }
        __syncthreads();
    }

    const float inv0 = hm / l0, inv1 = hm / l1;
    const int row0 = si + wid * 16 + g, row1 = row0 + 8;
    #pragma unroll
    for (int d = 0; d < 8; d++) {
        int col = h * 64 + d * 8 + tig * 2;
        uint32_t h2, l2;
        split2h(acc[d][0] * inv0, acc[d][1] * inv0, h2, l2);
        size_t o0 = (size_t)(b * SS + row0) * DD + col;
        *(uint32_t*)&Ch[o0] = h2;
        *(uint32_t*)&Cl[o0] = l2;
        split2h(acc[d][2] * inv1, acc[d][3] * inv1, h2, l2);
        size_t o1 = (size_t)(b * SS + row1) * DD + col;
        *(uint32_t*)&Ch[o1] = h2;
        *(uint32_t*)&Cl[o1] = l2;
    }
}

// ================== residual + LayerNorm (+ fp16 split outputs) ==================
__global__ __launch_bounds__(256) void ln_residual(
    const float* __restrict__ x, const float* __restrict__ y,
    const float* __restrict__ g, const float* __restrict__ b,
    float* __restrict__ out, __half* __restrict__ oh,
    __half* __restrict__ ol)
{
    const int row = blockIdx.x;
    const int tid = threadIdx.x;
    const float4* xp = (const float4*)(x + (size_t)row * DD);
    const float4* yp = (const float4*)(y + (size_t)row * DD);

    float4 xv = xp[tid];
    float4 yv = yp[tid];
    float4 s4 = make_float4(xv.x + yv.x, xv.y + yv.y, xv.z + yv.z, xv.w + yv.w);

    float s  = s4.x + s4.y + s4.z + s4.w;
    float ss = s4.x * s4.x + s4.y * s4.y + s4.z * s4.z + s4.w * s4.w;

    const int lane = tid & 31, warp = tid >> 5;
    #pragma unroll
    for (int off = 16; off > 0; off >>= 1) {
        s  += __shfl_xor_sync(0xffffffffu, s, off);
        ss += __shfl_xor_sync(0xffffffffu, ss, off);
    }
    __shared__ float ws[8], wss[8];
    if (lane == 0) { ws[warp] = s; wss[warp] = ss; }
    __syncthreads();
    if (warp == 0) {
        float a  = (lane < 8) ? ws[lane]  : 0.f;
        float aa = (lane < 8) ? wss[lane] : 0.f;
        #pragma unroll
        for (int off = 4; off > 0; off >>= 1) {
            a  += __shfl_xor_sync(0xffffffffu, a, off);
            aa += __shfl_xor_sync(0xffffffffu, aa, off);
        }
        if (lane == 0) { ws[0] = a; wss[0] = aa; }
    }
    __syncthreads();
    const float mean = ws[0] * (1.0f / DD);
    const float var  = wss[0] * (1.0f / DD) - mean * mean;
    const float inv  = rsqrtf(var + 1e-12f);

    const float4 gv = ((const float4*)g)[tid];
    const float4 bv = ((const float4*)b)[tid];
    float4 o;
    o.x = (s4.x - mean) * inv * gv.x + bv.x;
    o.y = (s4.y - mean) * inv * gv.y + bv.y;
    o.z = (s4.z - mean) * inv * gv.z + bv.z;
    o.w = (s4.w - mean) * inv * gv.w + bv.w;
    ((float4*)(out + (size_t)row * DD))[tid] = o;

    uint32_t h01, l01, h23, l23;
    split2h(o.x, o.y, h01, l01);
    split2h(o.z, o.w, h23, l23);
    uint32_t* hp = (uint32_t*)(oh + (size_t)row * DD);
    uint32_t* lp = (uint32_t*)(ol + (size_t)row * DD);
    hp[tid * 2] = h01; hp[tid * 2 + 1] = h23;
    lp[tid * 2] = l01; lp[tid * 2 + 1] = l23;
}

// ================== host orchestration ==================
extern "C" void kernel_launch(void* const* d_in, const int* in_sizes, int n_in,
                              void* d_out, int out_size)
{
    const float* hidden = (const float*)d_in[0];
    const float* amask  = (const float*)d_in[1];
    const float* hmask  = (const float*)d_in[2];
    const float* q_w    = (const float*)d_in[3];
    const float* q_b    = (const float*)d_in[4];
    const float* k_w    = (const float*)d_in[5];
    const float* k_b    = (const float*)d_in[6];
    const float* v_w    = (const float*)d_in[7];
    const float* v_b    = (const float*)d_in[8];
    const float* o_w    = (const float*)d_in[9];
    const float* o_b    = (const float*)d_in[10];
    const float* aln_g  = (const float*)d_in[11];
    const float* aln_b  = (const float*)d_in[12];
    const float* w1     = (const float*)d_in[13];
    const float* b1     = (const float*)d_in[14];
    const float* w2     = (const float*)d_in[15];
    const float* b2     = (const float*)d_in[16];
    const float* fln_g  = (const float*)d_in[17];
    const float* fln_b  = (const float*)d_in[18];
    float* out = (float*)d_out;

    float *tmpb, *attnb, *hsb, *bqkvb;
    __half *hs_h, *hs_l, *qkv_h, *qkv_l;
    __half *ctx_h, *ctx_l, *attn_h, *attn_l, *ffn1_h, *ffn1_l;
    __half *wqkvb, *wob, *w1b, *w2b;
    cudaGetSymbolAddress((void**)&tmpb,  g_tmp);
    cudaGetSymbolAddress((void**)&attnb, g_attn);
    cudaGetSymbolAddress((void**)&hsb,   g_hs);
    cudaGetSymbolAddress((void**)&bqkvb, g_bqkv);
    cudaGetSymbolAddress((void**)&hs_h, g_hs_h);   cudaGetSymbolAddress((void**)&hs_l, g_hs_l);
    cudaGetSymbolAddress((void**)&qkv_h, g_qkv_h); cudaGetSymbolAddress((void**)&qkv_l, g_qkv_l);
    cudaGetSymbolAddress((void**)&ctx_h, g_ctx_h); cudaGetSymbolAddress((void**)&ctx_l, g_ctx_l);
    cudaGetSymbolAddress((void**)&attn_h, g_attn_h); cudaGetSymbolAddress((void**)&attn_l, g_attn_l);
    cudaGetSymbolAddress((void**)&ffn1_h, g_ffn1_h); cudaGetSymbolAddress((void**)&ffn1_l, g_ffn1_l);
    cudaGetSymbolAddress((void**)&wqkvb, g_wqkv);
    cudaGetSymbolAddress((void**)&wob, g_wo);
    cudaGetSymbolAddress((void**)&w1b, g_w1);
    cudaGetSymbolAddress((void**)&w2b, g_w2);

    cudaFuncSetAttribute(gemm_fp16x2<0,0,1>, cudaFuncAttributeMaxDynamicSharedMemorySize, 2*GM_STAGE);
    cudaFuncSetAttribute(gemm_fp16x2<0,1,0>, cudaFuncAttributeMaxDynamicSharedMemorySize, 2*GM_STAGE);
    cudaFuncSetAttribute(gemm_fp16x2<1,0,1>, cudaFuncAttributeMaxDynamicSharedMemorySize, 2*GM_STAGE);
    cudaFuncSetAttribute(flash_attn, cudaFuncAttributeMaxDynamicSharedMemorySize, FA_SMEM);

    pack_qkv_w<<<(DD*QKVN/4)/256, 256>>>(q_w, k_w, v_w, wqkvb);
    pack_qkv_b<<<QKVN/256, 256>>>(q_b, k_b, v_b, bqkvb);
    cvt_fp16<<<(DD*DD)/1024, 256>>>(o_w, wob);
    cvt_fp16<<<(LL*DD*DFF)/1024, 256>>>(w1, w1b);
    cvt_fp16<<<(LL*DFF*DD)/1024, 256>>>(w2, w2b);
    split_fp16<<<(MM*DD)/1024, 256>>>(hidden, hs_h, hs_l);

    const dim3 g1(DD/128, MM/128);
    const dim3 g4(DFF/128, MM/128);
    const dim3 gqkv(QKVN/128, MM/128);
    const dim3 fa_grid(SS/128, BB*HH);

    for (int l = 0; l < LL; l++) {
        const float* hsin_f = (l == 0) ? hidden : hsb;
        float* hsout = (l == LL - 1) ? out : hsb;

        gemm_fp16x2<0,0,1><<<gqkv, 256, 2*GM_STAGE>>>(hs_h, hs_l, wqkvb,
            bqkvb, nullptr, qkv_h, qkv_l, MM, QKVN, DD);

        flash_attn<<<fa_grid, 256, FA_SMEM>>>(qkv_h, qkv_l, amask, hmask, l,
                                              ctx_h, ctx_l);

        gemm_fp16x2<0,1,0><<<g1, 256, 2*GM_STAGE>>>(ctx_h, ctx_l, wob, o_b,
            tmpb, nullptr, nullptr, MM, DD, DD);
        ln_residual<<<MM, 256>>>(hsin_f, tmpb, aln_g, aln_b, attnb, attn_h, attn_l);

        gemm_fp16x2<1,0,1><<<g4, 256, 2*GM_STAGE>>>(attn_h, attn_l,
            w1b + (size_t)l*DD*DFF, b1 + (size_t)l*DFF,
            nullptr, ffn1_h, ffn1_l, MM, DFF, DD);
        gemm_fp16x2<0,1,0><<<g1, 256, 2*GM_STAGE>>>(ffn1_h, ffn1_l,
            w2b + (size_t)l*DFF*DD, b2 + (size_t)l*DD,
            tmpb, nullptr, nullptr, MM, DD, DFF);
        ln_residual<<<MM, 256>>>(attnb, tmpb, fln_g + (size_t)l*DD,
                                 fln_b + (size_t)l*DD, hsout, hs_h, hs_l);
    }
}

// round 9
// speedup vs baseline: 2.4486x; 1.6450x over previous
#include <cuda_runtime.h>
#include <cuda_fp16.h>
#include <math.h>
#include <stdint.h>

// ---------------- problem constants ----------------
#define BB   4
#define SS   1024
#define DD   1024
#define HH   16
#define HDIM 64
#define LL   2
#define DFF  4096
#define MM   (BB*SS)
#define QKVN 3072

// ---------------- static device scratch ----------------
__device__ __align__(256) float g_tmp [(size_t)MM*DD];
__device__ __align__(256) float g_attn[(size_t)MM*DD];
__device__ __align__(256) float g_hs  [(size_t)MM*DD];

__device__ __align__(256) __half g_hsh [(size_t)MM*DD];
__device__ __align__(256) __half g_qkv [(size_t)MM*QKVN];
__device__ __align__(256) __half g_ctx [(size_t)MM*DD];
__device__ __align__(256) __half g_attnh[(size_t)MM*DD];
__device__ __align__(256) __half g_ffn1[(size_t)MM*DFF];

__device__ __align__(256) __half g_wqkv[(size_t)DD*QKVN];
__device__ __align__(256) float  g_bqkv[QKVN];
__device__ __align__(256) __half g_wo  [(size_t)DD*DD];
__device__ __align__(256) __half g_w1  [(size_t)LL*DD*DFF];
__device__ __align__(256) __half g_w2  [(size_t)LL*DFF*DD];

// ---------------- asm helpers ----------------
__device__ __forceinline__ uint32_t smem_u32(const void* p) {
    uint32_t a;
    asm("{ .reg .u64 t; cvta.to.shared.u64 t, %1; cvt.u32.u64 %0, t; }"
        : "=r"(a) : "l"(p));
    return a;
}
#define CP16(dst, src) asm volatile("cp.async.cg.shared.global [%0], [%1], 16;" :: "r"(dst), "l"(src) : "memory")
#define CPCOMMIT()     asm volatile("cp.async.commit_group;" ::: "memory")
#define CPWAIT1()      asm volatile("cp.async.wait_group 1;" ::: "memory")
#define CPWAIT0()      asm volatile("cp.async.wait_group 0;" ::: "memory")

__device__ __forceinline__ void ldsm4(uint32_t* r, uint32_t a) {
    asm volatile("ldmatrix.sync.aligned.m8n8.x4.shared.b16 {%0,%1,%2,%3}, [%4];"
        : "=r"(r[0]), "=r"(r[1]), "=r"(r[2]), "=r"(r[3]) : "r"(a));
}
__device__ __forceinline__ void ldsm4t(uint32_t* r, uint32_t a) {
    asm volatile("ldmatrix.sync.aligned.m8n8.x4.trans.shared.b16 {%0,%1,%2,%3}, [%4];"
        : "=r"(r[0]), "=r"(r[1]), "=r"(r[2]), "=r"(r[3]) : "r"(a));
}
__device__ __forceinline__ void mma_f16(float* c, const uint32_t* a, const uint32_t* b) {
    asm volatile(
        "mma.sync.aligned.m16n8k16.row.col.f32.f16.f16.f32 "
        "{%0,%1,%2,%3}, {%4,%5,%6,%7}, {%8,%9}, {%0,%1,%2,%3};"
        : "+f"(c[0]), "+f"(c[1]), "+f"(c[2]), "+f"(c[3])
        : "r"(a[0]), "r"(a[1]), "r"(a[2]), "r"(a[3]), "r"(b[0]), "r"(b[1]));
}
__device__ __forceinline__ float gelu_exact(float x) {
    return 0.5f * x * (1.0f + erff(x * 0.70710678118654752440f));
}
__device__ __forceinline__ uint32_t pack2h(float v0, float v1) {
    __half2 p = __floats2half2_rn(v0, v1);
    return *reinterpret_cast<uint32_t*>(&p);
}

// ================== convert: fp32 -> fp16 ==================
__global__ __launch_bounds__(256) void cvt_fp16(
    const float* __restrict__ src, __half* __restrict__ dst)
{
    int idx = blockIdx.x * 256 + threadIdx.x;
    float4 v = ((const float4*)src)[idx];
    ((uint32_t*)dst)[idx * 2]     = pack2h(v.x, v.y);
    ((uint32_t*)dst)[idx * 2 + 1] = pack2h(v.z, v.w);
}

// ================== pack QKV weights: [D,3D] fp16 ==================
__global__ __launch_bounds__(256) void pack_qkv_w(
    const float* __restrict__ q, const float* __restrict__ k,
    const float* __restrict__ v, __half* __restrict__ dst)
{
    int i4 = blockIdx.x * 256 + threadIdx.x;
    int row = i4 / (QKVN / 4);
    int c   = (i4 % (QKVN / 4)) * 4;
    const float* src = (c < 1024) ? q + (size_t)row * 1024 + c
                     : (c < 2048) ? k + (size_t)row * 1024 + (c - 1024)
                                  : v + (size_t)row * 1024 + (c - 2048);
    float4 vv = *(const float4*)src;
    ((uint32_t*)dst)[i4 * 2]     = pack2h(vv.x, vv.y);
    ((uint32_t*)dst)[i4 * 2 + 1] = pack2h(vv.z, vv.w);
}
__global__ __launch_bounds__(256) void pack_qkv_b(
    const float* __restrict__ q, const float* __restrict__ k,
    const float* __restrict__ v, float* __restrict__ o)
{
    int idx = blockIdx.x * 256 + threadIdx.x;
    o[idx] = (idx < 1024) ? q[idx] : (idx < 2048) ? k[idx - 1024] : v[idx - 2048];
}

// ================== GEMM: C = A*B + bias, fp16 via mma.sync ==================
// 128x128 tile, 256 threads, 2(m)x4(n) warps, BK=32, double-buffered, occ 2.
// stage: A[128][80B] + B[32][272B] = 18944 B
#define GM_STAGE 18944
template<int ACT, int WF32, int WHALF>
__global__ __launch_bounds__(256, 2) void gemm_fp16(
    const __half* __restrict__ Aa, const __half* __restrict__ Bw,
    const float* __restrict__ bias,
    float* __restrict__ Cf, __half* __restrict__ Chf,
    int M, int N, int K)
{
    extern __shared__ char sm[];
    const uint32_t smb = smem_u32(sm);
    const int tid = threadIdx.x, lane = tid & 31, wid = tid >> 5;
    const int warp_m = wid >> 2, warp_n = wid & 3;
    const int bm = blockIdx.y * 128, bn = blockIdx.x * 128;

    float c[4][4][4];
    #pragma unroll
    for (int i = 0; i < 4; i++)
        #pragma unroll
        for (int j = 0; j < 4; j++)
            #pragma unroll
            for (int q = 0; q < 4; q++) c[i][j][q] = 0.f;

    const int rowA  = (lane & 7) + ((lane >> 3) & 1) * 8;
    const int kselA = (lane >> 4) * 8;
    const int kB    = (lane & 7) + ((lane >> 3) & 1) * 8;
    const int nB    = ((lane >> 4) & 1) * 8;

    auto load_stage = [&](int s, int k0) {
        uint32_t base = smb + s * GM_STAGE;
        {
            int cidx = tid;            // 512 float4 slots for A: 128 rows x 4
            int row = cidx >> 2, kc = (cidx & 3) << 3;
            size_t g = (size_t)(bm + row) * K + k0 + kc;
            CP16(base + row * 80 + kc * 2, Aa + g);
            int cidx2 = tid + 256;
            int row2 = cidx2 >> 2, kc2 = (cidx2 & 3) << 3;
            size_t g2 = (size_t)(bm + row2) * K + k0 + kc2;
            CP16(base + row2 * 80 + kc2 * 2, Aa + g2);
        }
        #pragma unroll
        for (int i = 0; i < 2; i++) {
            int cidx = tid + i * 256;
            int k = cidx >> 4, nc = (cidx & 15) << 3;
            size_t g = (size_t)(k0 + k) * N + bn + nc;
            CP16(base + 10240 + k * 272 + nc * 2, Bw + g);
        }
        CPCOMMIT();
    };

    auto compute = [&](int s) {
        uint32_t bA = smb + s * GM_STAGE;
        uint32_t bB = bA + 10240;
        #pragma unroll
        for (int ks = 0; ks < 2; ks++) {
            uint32_t bf[4][2];
            #pragma unroll
            for (int ntp = 0; ntp < 2; ntp++) {
                uint32_t off = (uint32_t)((ks * 16 + kB) * 272 +
                                          (warp_n * 32 + ntp * 16 + nB) * 2);
                uint32_t r[4];
                ldsm4t(r, bB + off);
                bf[2*ntp][0] = r[0]; bf[2*ntp][1] = r[1];
                bf[2*ntp+1][0] = r[2]; bf[2*ntp+1][1] = r[3];
            }
            #pragma unroll
            for (int mt = 0; mt < 4; mt++) {
                uint32_t off = (uint32_t)((warp_m * 64 + mt * 16 + rowA) * 80 +
                                          (ks * 16 + kselA) * 2);
                uint32_t af[4];
                ldsm4(af, bA + off);
                #pragma unroll
                for (int nt = 0; nt < 4; nt++)
                    mma_f16(c[mt][nt], af, bf[nt]);
            }
        }
    };

    const int nt_k = K >> 5;
    load_stage(0, 0);
    for (int t = 0; t < nt_k; t++) {
        if (t + 1 < nt_k) { load_stage((t + 1) & 1, (t + 1) << 5); CPWAIT1(); }
        else              { CPWAIT0(); }
        __syncthreads();
        compute(t & 1);
        __syncthreads();
    }

    const int g = lane >> 2, tig = lane & 3;
    #pragma unroll
    for (int mt = 0; mt < 4; mt++) {
        #pragma unroll
        for (int nt = 0; nt < 4; nt++) {
            int col = bn + warp_n * 32 + nt * 8 + tig * 2;
            float b0 = bias[col], b1 = bias[col + 1];
            #pragma unroll
            for (int half = 0; half < 2; half++) {
                int row = bm + warp_m * 64 + mt * 16 + g + half * 8;
                float v0 = c[mt][nt][half * 2 + 0] + b0;
                float v1 = c[mt][nt][half * 2 + 1] + b1;
                if (ACT) { v0 = gelu_exact(v0); v1 = gelu_exact(v1); }
                if (WF32)
                    *(float2*)&Cf[(size_t)row * N + col] = make_float2(v0, v1);
                if (WHALF)
                    *(uint32_t*)&Chf[(size_t)row * N + col] = pack2h(v0, v1);
            }
        }
    }
}

// ================== fused flash attention (fp16) ==================
// Q, K, V, P all single fp16; fp32 softmax statistics.
// smem: Q 18432 | 2 stages x [K 18432 | V 18432] | mask 4096
#define FA_Q    0
#define FA_K(s) (18432 + (s) * 36864)
#define FA_MASK 92160
#define FA_SMEM 96256

__global__ __launch_bounds__(256) void flash_attn(
    const __half* __restrict__ qkv,
    const float* __restrict__ mask, const float* __restrict__ head_mask,
    int layer, __half* __restrict__ Cc)
{
    extern __shared__ char sm[];
    const uint32_t smb = smem_u32(sm);
    const float* sm_mask = (const float*)(sm + FA_MASK);
    const int tid = threadIdx.x, lane = tid & 31, wid = tid >> 5;
    const int bh = blockIdx.y, b = bh >> 4, h = bh & 15;
    const int si = blockIdx.x * 128;
    const float hm = head_mask[layer * HH + h];

    #pragma unroll
    for (int i = 0; i < 4; i++) {
        int idx = tid + i * 256;
        int r = idx >> 3, cc = (idx & 7) << 3;
        size_t gq = (size_t)(b * SS + si + r) * QKVN + h * 64 + cc;
        CP16(smb + FA_Q + r * 144 + cc * 2, qkv + gq);
    }
    CP16(smb + FA_MASK + tid * 16, mask + b * SS + tid * 4);

    auto load_kv = [&](int s, int t0) {
        uint32_t base = smb + FA_K(s);
        #pragma unroll
        for (int i = 0; i < 4; i++) {
            int idx = tid + i * 256;
            int r = idx >> 3, cc = (idx & 7) << 3;
            size_t gk = (size_t)(b * SS + t0 + r) * QKVN + 1024 + h * 64 + cc;
            size_t gv = (size_t)(b * SS + t0 + r) * QKVN + 2048 + h * 64 + cc;
            CP16(base + r * 144 + cc * 2, qkv + gk);
            CP16(base + 18432 + r * 144 + cc * 2, qkv + gv);
        }
        CPCOMMIT();
    };
    load_kv(0, 0);

    const int rowA  = (lane & 7) + ((lane >> 3) & 1) * 8;
    const int kselA = (lane >> 4) * 8;
    const int rowK  = (lane & 7) + ((lane >> 4) & 1) * 8;
    const int dselK = ((lane >> 3) & 1) * 8;
    const int kB    = (lane & 7) + ((lane >> 3) & 1) * 8;
    const int nB    = ((lane >> 4) & 1) * 8;
    const int g = lane >> 2, tig = lane & 3;

    float m_prev0 = -INFINITY, m_prev1 = -INFINITY;
    float l0 = 0.f, l1 = 0.f;
    float acc[8][4];
    #pragma unroll
    for (int i = 0; i < 8; i++)
        #pragma unroll
        for (int q = 0; q < 4; q++) acc[i][q] = 0.f;

    const float scale = 0.125f;

    for (int kc = 0; kc < SS / 128; kc++) {
        const int s = kc & 1;
        if (kc + 1 < SS / 128) { load_kv((kc + 1) & 1, (kc + 1) * 128); CPWAIT1(); }
        else                   { CPWAIT0(); }
        __syncthreads();

        float c[16][4];
        #pragma unroll
        for (int i = 0; i < 16; i++)
            #pragma unroll
            for (int q = 0; q < 4; q++) c[i][q] = 0.f;

        uint32_t kb = smb + FA_K(s);
        #pragma unroll
        for (int ks = 0; ks < 4; ks++) {
            uint32_t af[4];
            uint32_t offa = (uint32_t)((wid * 16 + rowA) * 144 + (ks * 16 + kselA) * 2);
            ldsm4(af, smb + FA_Q + offa);
            #pragma unroll
            for (int ntp = 0; ntp < 8; ntp++) {
                uint32_t offb = (uint32_t)((ntp * 16 + rowK) * 144 + (ks * 16 + dselK) * 2);
                uint32_t r4[4];
                ldsm4(r4, kb + offb);
                uint32_t be[2] = { r4[0], r4[1] }, bo[2] = { r4[2], r4[3] };
                mma_f16(c[2*ntp],   af, be);
                mma_f16(c[2*ntp+1], af, bo);
            }
        }

        float mx0 = -INFINITY, mx1 = -INFINITY;
        #pragma unroll
        for (int nt = 0; nt < 16; nt++) {
            int col = kc * 128 + nt * 8 + tig * 2;
            float mk0 = sm_mask[col], mk1 = sm_mask[col + 1];
            c[nt][0] = c[nt][0] * scale + mk0;
            c[nt][1] = c[nt][1] * scale + mk1;
            c[nt][2] = c[nt][2] * scale + mk0;
            c[nt][3] = c[nt][3] * scale + mk1;
            mx0 = fmaxf(mx0, fmaxf(c[nt][0], c[nt][1]));
            mx1 = fmaxf(mx1, fmaxf(c[nt][2], c[nt][3]));
        }
        mx0 = fmaxf(mx0, __shfl_xor_sync(0xffffffffu, mx0, 1));
        mx0 = fmaxf(mx0, __shfl_xor_sync(0xffffffffu, mx0, 2));
        mx1 = fmaxf(mx1, __shfl_xor_sync(0xffffffffu, mx1, 1));
        mx1 = fmaxf(mx1, __shfl_xor_sync(0xffffffffu, mx1, 2));

        float mn0 = fmaxf(m_prev0, mx0), mn1 = fmaxf(m_prev1, mx1);
        float al0 = __expf(m_prev0 - mn0), al1 = __expf(m_prev1 - mn1);
        m_prev0 = mn0; m_prev1 = mn1;

        float s0 = 0.f, s1 = 0.f;
        #pragma unroll
        for (int nt = 0; nt < 16; nt++) {
            c[nt][0] = __expf(c[nt][0] - mn0);
            c[nt][1] = __expf(c[nt][1] - mn0);
            c[nt][2] = __expf(c[nt][2] - mn1);
            c[nt][3] = __expf(c[nt][3] - mn1);
            s0 += c[nt][0] + c[nt][1];
            s1 += c[nt][2] + c[nt][3];
        }
        s0 += __shfl_xor_sync(0xffffffffu, s0, 1);
        s0 += __shfl_xor_sync(0xffffffffu, s0, 2);
        s1 += __shfl_xor_sync(0xffffffffu, s1, 1);
        s1 += __shfl_xor_sync(0xffffffffu, s1, 2);
        l0 = l0 * al0 + s0;
        l1 = l1 * al1 + s1;

        #pragma unroll
        for (int d = 0; d < 8; d++) {
            acc[d][0] *= al0; acc[d][1] *= al0;
            acc[d][2] *= al1; acc[d][3] *= al1;
        }

        uint32_t vb = smb + FA_K(s) + 18432;
        #pragma unroll
        for (int ks2 = 0; ks2 < 8; ks2++) {
            uint32_t pa[4];
            pa[0] = pack2h(c[2*ks2][0],   c[2*ks2][1]);
            pa[1] = pack2h(c[2*ks2][2],   c[2*ks2][3]);
            pa[2] = pack2h(c[2*ks2+1][0], c[2*ks2+1][1]);
            pa[3] = pack2h(c[2*ks2+1][2], c[2*ks2+1][3]);
            #pragma unroll
            for (int ntp2 = 0; ntp2 < 4; ntp2++) {
                uint32_t offv = (uint32_t)((ks2 * 16 + kB) * 144 + (ntp2 * 16 + nB) * 2);
                uint32_t r4[4];
                ldsm4t(r4, vb + offv);
                uint32_t ve[2] = { r4[0], r4[1] }, vo[2] = { r4[2], r4[3] };
                mma_f16(acc[2*ntp2],   pa, ve);
                mma_f16(acc[2*ntp2+1], pa, vo);
            }
        }
        __syncthreads();
    }

    const float inv0 = hm / l0, inv1 = hm / l1;
    const int row0 = si + wid * 16 + g, row1 = row0 + 8;
    #pragma unroll
    for (int d = 0; d < 8; d++) {
        int col = h * 64 + d * 8 + tig * 2;
        size_t o0 = (size_t)(b * SS + row0) * DD + col;
        *(uint32_t*)&Cc[o0] = pack2h(acc[d][0] * inv0, acc[d][1] * inv0);
        size_t o1 = (size_t)(b * SS + row1) * DD + col;
        *(uint32_t*)&Cc[o1] = pack2h(acc[d][2] * inv1, acc[d][3] * inv1);
    }
}

// ================== residual + LayerNorm (+ fp16 output) ==================
__global__ __launch_bounds__(256) void ln_residual(
    const float* __restrict__ x, const float* __restrict__ y,
    const float* __restrict__ g, const float* __restrict__ b,
    float* __restrict__ out, __half* __restrict__ oh)
{
    const int row = blockIdx.x;
    const int tid = threadIdx.x;
    const float4* xp = (const float4*)(x + (size_t)row * DD);
    const float4* yp = (const float4*)(y + (size_t)row * DD);

    float4 xv = xp[tid];
    float4 yv = yp[tid];
    float4 s4 = make_float4(xv.x + yv.x, xv.y + yv.y, xv.z + yv.z, xv.w + yv.w);

    float s  = s4.x + s4.y + s4.z + s4.w;
    float ss = s4.x * s4.x + s4.y * s4.y + s4.z * s4.z + s4.w * s4.w;

    const int lane = tid & 31, warp = tid >> 5;
    #pragma unroll
    for (int off = 16; off > 0; off >>= 1) {
        s  += __shfl_xor_sync(0xffffffffu, s, off);
        ss += __shfl_xor_sync(0xffffffffu, ss, off);
    }
    __shared__ float ws[8], wss[8];
    if (lane == 0) { ws[warp] = s; wss[warp] = ss; }
    __syncthreads();
    if (warp == 0) {
        float a  = (lane < 8) ? ws[lane]  : 0.f;
        float aa = (lane < 8) ? wss[lane] : 0.f;
        #pragma unroll
        for (int off = 4; off > 0; off >>= 1) {
            a  += __shfl_xor_sync(0xffffffffu, a, off);
            aa += __shfl_xor_sync(0xffffffffu, aa, off);
        }
        if (lane == 0) { ws[0] = a; wss[0] = aa; }
    }
    __syncthreads();
    const float mean = ws[0] * (1.0f / DD);
    const float var  = wss[0] * (1.0f / DD) - mean * mean;
    const float inv  = rsqrtf(var + 1e-12f);

    const float4 gv = ((const float4*)g)[tid];
    const float4 bv = ((const float4*)b)[tid];
    float4 o;
    o.x = (s4.x - mean) * inv * gv.x + bv.x;
    o.y = (s4.y - mean) * inv * gv.y + bv.y;
    o.z = (s4.z - mean) * inv * gv.z + bv.z;
    o.w = (s4.w - mean) * inv * gv.w + bv.w;
    ((float4*)(out + (size_t)row * DD))[tid] = o;

    uint32_t* hp = (uint32_t*)(oh + (size_t)row * DD);
    hp[tid * 2]     = pack2h(o.x, o.y);
    hp[tid * 2 + 1] = pack2h(o.z, o.w);
}

// ================== host orchestration ==================
extern "C" void kernel_launch(void* const* d_in, const int* in_sizes, int n_in,
                              void* d_out, int out_size)
{
    const float* hidden = (const float*)d_in[0];
    const float* amask  = (const float*)d_in[1];
    const float* hmask  = (const float*)d_in[2];
    const float* q_w    = (const float*)d_in[3];
    const float* q_b    = (const float*)d_in[4];
    const float* k_w    = (const float*)d_in[5];
    const float* k_b    = (const float*)d_in[6];
    const float* v_w    = (const float*)d_in[7];
    const float* v_b    = (const float*)d_in[8];
    const float* o_w    = (const float*)d_in[9];
    const float* o_b    = (const float*)d_in[10];
    const float* aln_g  = (const float*)d_in[11];
    const float* aln_b  = (const float*)d_in[12];
    const float* w1     = (const float*)d_in[13];
    const float* b1     = (const float*)d_in[14];
    const float* w2     = (const float*)d_in[15];
    const float* b2     = (const float*)d_in[16];
    const float* fln_g  = (const float*)d_in[17];
    const float* fln_b  = (const float*)d_in[18];
    float* out = (float*)d_out;

    float *tmpb, *attnb, *hsb, *bqkvb;
    __half *hsh, *qkvb, *ctxb, *attnh, *ffn1b;
    __half *wqkvb, *wob, *w1b, *w2b;
    cudaGetSymbolAddress((void**)&tmpb,  g_tmp);
    cudaGetSymbolAddress((void**)&attnb, g_attn);
    cudaGetSymbolAddress((void**)&hsb,   g_hs);
    cudaGetSymbolAddress((void**)&bqkvb, g_bqkv);
    cudaGetSymbolAddress((void**)&hsh,   g_hsh);
    cudaGetSymbolAddress((void**)&qkvb,  g_qkv);
    cudaGetSymbolAddress((void**)&ctxb,  g_ctx);
    cudaGetSymbolAddress((void**)&attnh, g_attnh);
    cudaGetSymbolAddress((void**)&ffn1b, g_ffn1);
    cudaGetSymbolAddress((void**)&wqkvb, g_wqkv);
    cudaGetSymbolAddress((void**)&wob,   g_wo);
    cudaGetSymbolAddress((void**)&w1b,   g_w1);
    cudaGetSymbolAddress((void**)&w2b,   g_w2);

    cudaFuncSetAttribute(gemm_fp16<0,0,1>, cudaFuncAttributeMaxDynamicSharedMemorySize, 2*GM_STAGE);
    cudaFuncSetAttribute(gemm_fp16<0,1,0>, cudaFuncAttributeMaxDynamicSharedMemorySize, 2*GM_STAGE);
    cudaFuncSetAttribute(gemm_fp16<1,0,1>, cudaFuncAttributeMaxDynamicSharedMemorySize, 2*GM_STAGE);
    cudaFuncSetAttribute(flash_attn, cudaFuncAttributeMaxDynamicSharedMemorySize, FA_SMEM);

    pack_qkv_w<<<(DD*QKVN/4)/256, 256>>>(q_w, k_w, v_w, wqkvb);
    pack_qkv_b<<<QKVN/256, 256>>>(q_b, k_b, v_b, bqkvb);
    cvt_fp16<<<(DD*DD)/1024, 256>>>(o_w, wob);
    cvt_fp16<<<(LL*DD*DFF)/1024, 256>>>(w1, w1b);
    cvt_fp16<<<(LL*DFF*DD)/1024, 256>>>(w2, w2b);
    cvt_fp16<<<(MM*DD)/1024, 256>>>(hidden, hsh);

    const dim3 g1(DD/128, MM/128);
    const dim3 g4(DFF/128, MM/128);
    const dim3 gqkv(QKVN/128, MM/128);
    const dim3 fa_grid(SS/128, BB*HH);

    for (int l = 0; l < LL; l++) {
        const float* hsin_f = (l == 0) ? hidden : hsb;
        float* hsout = (l == LL - 1) ? out : hsb;

        gemm_fp16<0,0,1><<<gqkv, 256, 2*GM_STAGE>>>(hsh, wqkvb, bqkvb,
            nullptr, qkvb, MM, QKVN, DD);

        flash_attn<<<fa_grid, 256, FA_SMEM>>>(qkvb, amask, hmask, l, ctxb);

        gemm_fp16<0,1,0><<<g1, 256, 2*GM_STAGE>>>(ctxb, wob, o_b,
            tmpb, nullptr, MM, DD, DD);
        ln_residual<<<MM, 256>>>(hsin_f, tmpb, aln_g, aln_b, attnb, attnh);

        gemm_fp16<1,0,1><<<g4, 256, 2*GM_STAGE>>>(attnh,
            w1b + (size_t)l*DD*DFF, b1 + (size_t)l*DFF,
            nullptr, ffn1b, MM, DFF, DD);
        gemm_fp16<0,1,0><<<g1, 256, 2*GM_STAGE>>>(ffn1b,
            w2b + (size_t)l*DFF*DD, b2 + (size_t)l*DD,
            tmpb, nullptr, MM, DD, DFF);
        ln_residual<<<MM, 256>>>(attnb, tmpb, fln_g + (size_t)l*DD,
                                 fln_b + (size_t)l*DD, hsout, hsh);
    }
}